// round 8
// baseline (speedup 1.0000x reference)
#include <cuda_runtime.h>
#include <cuda_bf16.h>
#include <math.h>
#include <stdint.h>

// Problem constants
#define BATCH   2
#define SEQ     2048
#define HID     2048
#define HEADS   16
#define HD      128
#define MROWS   (BATCH * SEQ)          // 4096
#define MSZ     ((size_t)MROWS * HID)  // 8M elements
#define WSZ     ((size_t)HID * HID)    // 4M elements

// f32 scratch
__device__ float g_Q[MSZ];
__device__ float g_K[MSZ];
__device__ float g_V[MSZ];
__device__ float g_A[MSZ];
// bf16 hi/lo split scratch
__device__ __nv_bfloat16 g_xh[MSZ],  g_xl[MSZ];
__device__ __nv_bfloat16 g_ah[MSZ],  g_al[MSZ];
__device__ __nv_bfloat16 g_Wh[4][WSZ], g_Wl[4][WSZ];

// ===========================================================================
// Helpers
// ===========================================================================
__device__ __forceinline__ uint32_t smem_u32(const void* p) {
    uint32_t a;
    asm("{ .reg .u64 t; cvta.to.shared.u64 t, %1; cvt.u32.u64 %0, t; }"
        : "=r"(a) : "l"(p));
    return a;
}

#define CP_ASYNC16(dst, src) \
    asm volatile("cp.async.cg.shared.global [%0], [%1], 16;" \
        :: "r"(dst), "l"(src))
#define CP_COMMIT() asm volatile("cp.async.commit_group;" ::: "memory")
#define CP_WAIT1()  asm volatile("cp.async.wait_group 1;" ::: "memory")

#define LDMATRIX_X4(r0, r1, r2, r3, addr) \
    asm volatile("ldmatrix.sync.aligned.m8n8.x4.shared.b16 {%0,%1,%2,%3}, [%4];" \
        : "=r"(r0), "=r"(r1), "=r"(r2), "=r"(r3) : "r"(addr))

#define MMA_BF16(c, a, b0, b1) \
    asm volatile("mma.sync.aligned.m16n8k16.row.col.f32.bf16.bf16.f32 " \
        "{%0,%1,%2,%3}, {%4,%5,%6,%7}, {%8,%9}, {%0,%1,%2,%3};" \
        : "+f"((c)[0]), "+f"((c)[1]), "+f"((c)[2]), "+f"((c)[3]) \
        : "r"((a)[0]), "r"((a)[1]), "r"((a)[2]), "r"((a)[3]), "r"(b0), "r"(b1))

// ===========================================================================
// f32 -> bf16 hi/lo split (elementwise, memory bound)
// ===========================================================================
__global__ __launch_bounds__(256) void split_bf16_kernel(
    const float* __restrict__ src, __nv_bfloat16* __restrict__ hi,
    __nv_bfloat16* __restrict__ lo, int n4)
{
    int i = blockIdx.x * blockDim.x + threadIdx.x;
    if (i >= n4) return;
    float4 v = reinterpret_cast<const float4*>(src)[i];
    __nv_bfloat16 h0 = __float2bfloat16_rn(v.x);
    __nv_bfloat16 h1 = __float2bfloat16_rn(v.y);
    __nv_bfloat16 h2 = __float2bfloat16_rn(v.z);
    __nv_bfloat16 h3 = __float2bfloat16_rn(v.w);
    uint2 hv;
    hv.x = (uint32_t)__bfloat16_as_ushort(h0) | ((uint32_t)__bfloat16_as_ushort(h1) << 16);
    hv.y = (uint32_t)__bfloat16_as_ushort(h2) | ((uint32_t)__bfloat16_as_ushort(h3) << 16);
    reinterpret_cast<uint2*>(hi)[i] = hv;
    __nv_bfloat162 l01 = __floats2bfloat162_rn(v.x - __bfloat162float(h0),
                                               v.y - __bfloat162float(h1));
    __nv_bfloat162 l23 = __floats2bfloat162_rn(v.z - __bfloat162float(h2),
                                               v.w - __bfloat162float(h3));
    uint2 lv;
    lv.x = *reinterpret_cast<uint32_t*>(&l01);
    lv.y = *reinterpret_cast<uint32_t*>(&l23);
    reinterpret_cast<uint2*>(lo)[i] = lv;
}

// ===========================================================================
// Split-bf16 tensor-core GEMM via mma.sync:
//   C[M,N] = Ah@Wh^T + Ah@Wl^T + Al@Wh^T + bias     (A:[M,K], W:[N,K] bf16)
// CTA 128x128, K-chunk 64, 8 warps (2x4), warp tile 64x32.
// cp.async double-buffered SMEM, padded stride 72 bf16 (144B, conflict-free).
// ===========================================================================
#define GM 128
#define GN 128
#define KC 64
#define NCHUNK (HID / KC)     // 32
#define GSTR 72               // padded bf16 row stride
#define TELEM (128 * GSTR)    // elems per tile (9216)
#define STAGE_ELEM (4 * TELEM)
#define GEMM_SMEM_B (2 * STAGE_ELEM * 2)   // 147456 bytes

__global__ __launch_bounds__(256) void gemm_mma(
    const __nv_bfloat16* __restrict__ Ah, const __nv_bfloat16* __restrict__ Al,
    const __nv_bfloat16* __restrict__ Wh, const __nv_bfloat16* __restrict__ Wl,
    const float* __restrict__ bias, float* __restrict__ C,
    int M, int N, int K)
{
    extern __shared__ __nv_bfloat16 sm[];
    const int tid  = threadIdx.x;
    const int lane = tid & 31;
    const int wid  = tid >> 5;
    const int warp_m = wid >> 2;      // 0..1
    const int warp_n = wid & 3;       // 0..3
    const int m0 = blockIdx.y * GM;
    const int n0 = blockIdx.x * GN;

    const uint32_t smb = smem_u32(sm);

    float acc[4][4][4];
    #pragma unroll
    for (int a = 0; a < 4; ++a)
        #pragma unroll
        for (int b = 0; b < 4; ++b)
            #pragma unroll
            for (int c = 0; c < 4; ++c) acc[a][b][c] = 0.0f;

    // Per-thread load mapping: 4 (row,col16B) slots per tile.
    int lrow[4], lcol[4];
    #pragma unroll
    for (int i = 0; i < 4; ++i) {
        int linear = tid + i * 256;       // 0..1023
        lrow[i] = linear >> 3;            // 0..127
        lcol[i] = (linear & 7) * 8;       // bf16 col, 16B granules
    }

    // Issue cp.async loads of chunk ck into stage s
    auto load_chunk = [&](int ck, int s) {
        const int k0 = ck * KC;
        uint32_t stage_b = smb + (uint32_t)s * STAGE_ELEM * 2;
        const __nv_bfloat16* gsrc[4] = {
            Ah + (size_t)m0 * K + k0, Al + (size_t)m0 * K + k0,
            Wh + (size_t)n0 * K + k0, Wl + (size_t)n0 * K + k0 };
        #pragma unroll
        for (int t = 0; t < 4; ++t) {
            uint32_t tb = stage_b + (uint32_t)t * TELEM * 2;
            #pragma unroll
            for (int i = 0; i < 4; ++i) {
                uint32_t dst = tb + (uint32_t)(lrow[i] * GSTR + lcol[i]) * 2;
                const __nv_bfloat16* src = gsrc[t] + (size_t)lrow[i] * K + lcol[i];
                CP_ASYNC16(dst, src);
            }
        }
    };

    load_chunk(0, 0); CP_COMMIT();
    load_chunk(1, 1); CP_COMMIT();

    // ldmatrix lane address components
    const int arow  = warp_m * 64 + (lane & 15);
    const int aksel = (lane >> 4) << 3;                        // 0 or 8
    const int brow  = warp_n * 32 + ((lane >> 4) << 3) + (lane & 7);
    const int bksel = ((lane >> 3) & 1) * 8;                   // 0 or 8

    for (int ck = 0; ck < NCHUNK; ++ck) {
        const int s = ck & 1;
        CP_WAIT1();
        __syncthreads();

        uint32_t stage_b = smb + (uint32_t)s * STAGE_ELEM * 2;
        uint32_t bAh = stage_b;
        uint32_t bAl = stage_b + TELEM * 2;
        uint32_t bWh = stage_b + 2 * TELEM * 2;
        uint32_t bWl = stage_b + 3 * TELEM * 2;

        #pragma unroll
        for (int ks = 0; ks < KC / 16; ++ks) {
            const int akoff = ks * 16 + aksel;
            const int bkoff = ks * 16 + bksel;

            uint32_t ah[4][4], al[4][4];
            #pragma unroll
            for (int a = 0; a < 4; ++a) {
                uint32_t off = (uint32_t)((arow + a * 16) * GSTR + akoff) * 2;
                LDMATRIX_X4(ah[a][0], ah[a][1], ah[a][2], ah[a][3], bAh + off);
                LDMATRIX_X4(al[a][0], al[a][1], al[a][2], al[a][3], bAl + off);
            }
            uint32_t bh[2][4], bl[2][4];
            #pragma unroll
            for (int p = 0; p < 2; ++p) {
                uint32_t off = (uint32_t)((brow + p * 16) * GSTR + bkoff) * 2;
                LDMATRIX_X4(bh[p][0], bh[p][1], bh[p][2], bh[p][3], bWh + off);
                LDMATRIX_X4(bl[p][0], bl[p][1], bl[p][2], bl[p][3], bWl + off);
            }
            #pragma unroll
            for (int a = 0; a < 4; ++a)
                #pragma unroll
                for (int p = 0; p < 2; ++p)
                    #pragma unroll
                    for (int hq = 0; hq < 2; ++hq) {
                        int nb = p * 2 + hq;
                        MMA_BF16(acc[a][nb], ah[a], bh[p][hq*2], bh[p][hq*2+1]);
                        MMA_BF16(acc[a][nb], ah[a], bl[p][hq*2], bl[p][hq*2+1]);
                        MMA_BF16(acc[a][nb], al[a], bh[p][hq*2], bh[p][hq*2+1]);
                    }
        }
        __syncthreads();
        if (ck + 2 < NCHUNK) load_chunk(ck + 2, s);
        CP_COMMIT();   // empty group OK at the tail; keeps wait_group 1 sound
    }

    // Epilogue: C-fragment rows (t/4, t/4+8), cols (t%4)*2..+1
    #pragma unroll
    for (int a = 0; a < 4; ++a) {
        int r_lo = m0 + warp_m * 64 + a * 16 + (lane >> 2);
        #pragma unroll
        for (int nb = 0; nb < 4; ++nb) {
            int c = n0 + warp_n * 32 + nb * 8 + (lane & 3) * 2;
            float2 blo = { bias[c], bias[c + 1] };
            float2 v0 = { acc[a][nb][0] + blo.x, acc[a][nb][1] + blo.y };
            float2 v1 = { acc[a][nb][2] + blo.x, acc[a][nb][3] + blo.y };
            *reinterpret_cast<float2*>(C + (size_t)r_lo * N + c) = v0;
            *reinterpret_cast<float2*>(C + (size_t)(r_lo + 8) * N + c) = v1;
        }
    }
}

// ---------------------------------------------------------------------------
// Flash attention (fp32, no mask) — unchanged from passing R4 kernel.
// ---------------------------------------------------------------------------
#define BQ  64
#define BKV 64
#define QK_PAD 1
#define V_PAD  4
#define P_PAD  4

#define QK_STR (HD + QK_PAD)   // 129
#define V_STR  (HD + V_PAD)    // 132
#define P_STR  (BKV + P_PAD)   // 68

#define SM_FLOATS (BQ*QK_STR + BKV*QK_STR + BKV*V_STR + BQ*P_STR)
#define SM_BYTES  (SM_FLOATS * 4)

__global__ __launch_bounds__(256) void flash_attn_f32(
    const float* __restrict__ Q, const float* __restrict__ K,
    const float* __restrict__ V, float* __restrict__ O, float scale)
{
    extern __shared__ float smf[];
    float* Qs = smf;
    float* Ks = Qs + BQ * QK_STR;
    float* Vs = Ks + BKV * QK_STR;
    float* Ps = Vs + BKV * V_STR;

    const int tid = threadIdx.x;
    const int tx = tid & 15;
    const int ty = tid >> 4;

    const int q0 = blockIdx.x * BQ;
    const int bh = blockIdx.y;
    const int b = bh / HEADS, h = bh % HEADS;
    const size_t base = ((size_t)b * SEQ) * HID + (size_t)h * HD;

    for (int idx = tid; idx < BQ * (HD / 4); idx += 256) {
        int r = idx / (HD / 4), c4 = idx % (HD / 4);
        float4 v = *reinterpret_cast<const float4*>(Q + base + (size_t)(q0 + r) * HID + c4 * 4);
        float* dst = &Qs[r * QK_STR + c4 * 4];
        dst[0] = v.x * scale; dst[1] = v.y * scale;
        dst[2] = v.z * scale; dst[3] = v.w * scale;
    }

    float m_i[4], l_i[4];
    #pragma unroll
    for (int i = 0; i < 4; ++i) { m_i[i] = -1e30f; l_i[i] = 0.0f; }
    float o_acc[4][8];
    #pragma unroll
    for (int i = 0; i < 4; ++i)
        #pragma unroll
        for (int j = 0; j < 8; ++j) o_acc[i][j] = 0.0f;

    for (int k0 = 0; k0 < SEQ; k0 += BKV) {
        __syncthreads();

        for (int idx = tid; idx < BKV * (HD / 4); idx += 256) {
            int r = idx / (HD / 4), c4 = idx % (HD / 4);
            float4 kv = *reinterpret_cast<const float4*>(K + base + (size_t)(k0 + r) * HID + c4 * 4);
            float4 vv = *reinterpret_cast<const float4*>(V + base + (size_t)(k0 + r) * HID + c4 * 4);
            float* kd = &Ks[r * QK_STR + c4 * 4];
            kd[0] = kv.x; kd[1] = kv.y; kd[2] = kv.z; kd[3] = kv.w;
            *reinterpret_cast<float4*>(&Vs[r * V_STR + c4 * 4]) = vv;
        }
        __syncthreads();

        float s[4][4];
        #pragma unroll
        for (int i = 0; i < 4; ++i)
            #pragma unroll
            for (int j = 0; j < 4; ++j) s[i][j] = 0.0f;

        for (int k = 0; k < HD; ++k) {
            float qf[4], kf[4];
            #pragma unroll
            for (int i = 0; i < 4; ++i) qf[i] = Qs[(ty * 4 + i) * QK_STR + k];
            #pragma unroll
            for (int j = 0; j < 4; ++j) kf[j] = Ks[(tx * 4 + j) * QK_STR + k];
            #pragma unroll
            for (int i = 0; i < 4; ++i)
                #pragma unroll
                for (int j = 0; j < 4; ++j)
                    s[i][j] += qf[i] * kf[j];
        }

        #pragma unroll
        for (int i = 0; i < 4; ++i) {
            float mx = s[i][0];
            #pragma unroll
            for (int j = 1; j < 4; ++j) mx = fmaxf(mx, s[i][j]);
            #pragma unroll
            for (int off = 8; off >= 1; off >>= 1)
                mx = fmaxf(mx, __shfl_xor_sync(0xffffffffu, mx, off, 16));

            float m_new = fmaxf(m_i[i], mx);
            float corr = __expf(m_i[i] - m_new);
            float rs = 0.0f;
            #pragma unroll
            for (int j = 0; j < 4; ++j) {
                float p = __expf(s[i][j] - m_new);
                s[i][j] = p; rs += p;
            }
            #pragma unroll
            for (int off = 8; off >= 1; off >>= 1)
                rs += __shfl_xor_sync(0xffffffffu, rs, off, 16);

            l_i[i] = l_i[i] * corr + rs;
            m_i[i] = m_new;
            #pragma unroll
            for (int j = 0; j < 8; ++j) o_acc[i][j] *= corr;
            #pragma unroll
            for (int j = 0; j < 4; ++j)
                Ps[(ty * 4 + i) * P_STR + tx * 4 + j] = s[i][j];
        }
        __syncthreads();

        for (int jk = 0; jk < BKV; ++jk) {
            float pv[4];
            #pragma unroll
            for (int i = 0; i < 4; ++i) pv[i] = Ps[(ty * 4 + i) * P_STR + jk];
            float4 v0 = *reinterpret_cast<const float4*>(&Vs[jk * V_STR + tx * 8]);
            float4 v1 = *reinterpret_cast<const float4*>(&Vs[jk * V_STR + tx * 8 + 4]);
            #pragma unroll
            for (int i = 0; i < 4; ++i) {
                o_acc[i][0] += pv[i] * v0.x;
                o_acc[i][1] += pv[i] * v0.y;
                o_acc[i][2] += pv[i] * v0.z;
                o_acc[i][3] += pv[i] * v0.w;
                o_acc[i][4] += pv[i] * v1.x;
                o_acc[i][5] += pv[i] * v1.y;
                o_acc[i][6] += pv[i] * v1.z;
                o_acc[i][7] += pv[i] * v1.w;
            }
        }
    }

    #pragma unroll
    for (int i = 0; i < 4; ++i) {
        float inv = 1.0f / l_i[i];
        size_t rbase = base + (size_t)(q0 + ty * 4 + i) * HID + tx * 8;
        float4 o0, o1;
        o0.x = o_acc[i][0] * inv; o0.y = o_acc[i][1] * inv;
        o0.z = o_acc[i][2] * inv; o0.w = o_acc[i][3] * inv;
        o1.x = o_acc[i][4] * inv; o1.y = o_acc[i][5] * inv;
        o1.z = o_acc[i][6] * inv; o1.w = o_acc[i][7] * inv;
        *reinterpret_cast<float4*>(O + rbase)     = o0;
        *reinterpret_cast<float4*>(O + rbase + 4) = o1;
    }
}

// ---------------------------------------------------------------------------
// Launch
// ---------------------------------------------------------------------------
extern "C" void kernel_launch(void* const* d_in, const int* in_sizes, int n_in,
                              void* d_out, int out_size)
{
    const float* x  = (const float*)d_in[0];
    const float* Wq = (const float*)d_in[1];
    const float* bq = (const float*)d_in[2];
    const float* Wk = (const float*)d_in[3];
    const float* bk = (const float*)d_in[4];
    const float* Wv = (const float*)d_in[5];
    const float* bv = (const float*)d_in[6];
    const float* Wo = (const float*)d_in[7];
    const float* bo = (const float*)d_in[8];
    float* out = (float*)d_out;

    float *Qb, *Kb, *Vb, *Ab;
    cudaGetSymbolAddress((void**)&Qb, g_Q);
    cudaGetSymbolAddress((void**)&Kb, g_K);
    cudaGetSymbolAddress((void**)&Vb, g_V);
    cudaGetSymbolAddress((void**)&Ab, g_A);
    __nv_bfloat16 *xh, *xl, *ah, *al, *Whb, *Wlb;
    cudaGetSymbolAddress((void**)&xh, g_xh);
    cudaGetSymbolAddress((void**)&xl, g_xl);
    cudaGetSymbolAddress((void**)&ah, g_ah);
    cudaGetSymbolAddress((void**)&al, g_al);
    cudaGetSymbolAddress((void**)&Whb, g_Wh);
    cudaGetSymbolAddress((void**)&Wlb, g_Wl);

    static int attr_set = 0;
    if (!attr_set) {
        cudaFuncSetAttribute(gemm_mma,
                             cudaFuncAttributeMaxDynamicSharedMemorySize, GEMM_SMEM_B);
        cudaFuncSetAttribute(flash_attn_f32,
                             cudaFuncAttributeMaxDynamicSharedMemorySize, SM_BYTES);
        attr_set = 1;
    }

    // Split conversions
    const int n4x = (int)(MSZ / 4), n4w = (int)(WSZ / 4);
    split_bf16_kernel<<<(n4x + 255) / 256, 256>>>(x, xh, xl, n4x);
    const float* Ws[4] = { Wq, Wk, Wv, Wo };
    for (int i = 0; i < 4; ++i)
        split_bf16_kernel<<<(n4w + 255) / 256, 256>>>(
            Ws[i], Whb + (size_t)i * WSZ, Wlb + (size_t)i * WSZ, n4w);

    dim3 ggrid(HID / GN, MROWS / GM);   // (16, 32)
    gemm_mma<<<ggrid, 256, GEMM_SMEM_B>>>(xh, xl, Whb + 0 * WSZ, Wlb + 0 * WSZ, bq, Qb, MROWS, HID, HID);
    gemm_mma<<<ggrid, 256, GEMM_SMEM_B>>>(xh, xl, Whb + 1 * WSZ, Wlb + 1 * WSZ, bk, Kb, MROWS, HID, HID);
    gemm_mma<<<ggrid, 256, GEMM_SMEM_B>>>(xh, xl, Whb + 2 * WSZ, Wlb + 2 * WSZ, bv, Vb, MROWS, HID, HID);

    const float scale = 1.0f / sqrtf((float)HD);
    dim3 agrid(SEQ / BQ, BATCH * HEADS);  // (32, 32)
    flash_attn_f32<<<agrid, 256, SM_BYTES>>>(Qb, Kb, Vb, Ab, scale);

    split_bf16_kernel<<<(n4x + 255) / 256, 256>>>(Ab, ah, al, n4x);
    gemm_mma<<<ggrid, 256, GEMM_SMEM_B>>>(ah, al, Whb + 3 * WSZ, Wlb + 3 * WSZ, bo, out, MROWS, HID, HID);
}

// round 12
// speedup vs baseline: 2.3443x; 2.3443x over previous
#include <cuda_runtime.h>
#include <cuda_bf16.h>
#include <math.h>
#include <stdint.h>

// Problem constants
#define BATCH   2
#define SEQ     2048
#define HID     2048
#define HEADS   16
#define HD      128
#define MROWS   (BATCH * SEQ)          // 4096
#define MSZ     ((size_t)MROWS * HID)  // 8M elements
#define WSZ     ((size_t)HID * HID)    // 4M elements

// bf16 hi/lo split scratch
__device__ __nv_bfloat16 g_xh[MSZ], g_xl[MSZ];
__device__ __nv_bfloat16 g_qh[MSZ], g_ql[MSZ];
__device__ __nv_bfloat16 g_kh[MSZ], g_kl[MSZ];
__device__ __nv_bfloat16 g_vh[MSZ], g_vl[MSZ];
__device__ __nv_bfloat16 g_ah[MSZ], g_al[MSZ];
__device__ __nv_bfloat16 g_Wh[4][WSZ], g_Wl[4][WSZ];

// ===========================================================================
// Helpers
// ===========================================================================
__device__ __forceinline__ uint32_t smem_u32(const void* p) {
    uint32_t a;
    asm("{ .reg .u64 t; cvta.to.shared.u64 t, %1; cvt.u32.u64 %0, t; }"
        : "=r"(a) : "l"(p));
    return a;
}

#define CP_ASYNC16(dst, src) \
    asm volatile("cp.async.cg.shared.global [%0], [%1], 16;" \
        :: "r"(dst), "l"(src))
#define CP_COMMIT() asm volatile("cp.async.commit_group;" ::: "memory")
#define CP_WAIT1()  asm volatile("cp.async.wait_group 1;" ::: "memory")
#define CP_WAIT2()  asm volatile("cp.async.wait_group 2;" ::: "memory")

#define LDMATRIX_X4(r0, r1, r2, r3, addr) \
    asm volatile("ldmatrix.sync.aligned.m8n8.x4.shared.b16 {%0,%1,%2,%3}, [%4];" \
        : "=r"(r0), "=r"(r1), "=r"(r2), "=r"(r3) : "r"(addr))

#define LDMATRIX_X4_T(r0, r1, r2, r3, addr) \
    asm volatile("ldmatrix.sync.aligned.m8n8.x4.trans.shared.b16 {%0,%1,%2,%3}, [%4];" \
        : "=r"(r0), "=r"(r1), "=r"(r2), "=r"(r3) : "r"(addr))

#define MMA_BF16(c, a, b0, b1) \
    asm volatile("mma.sync.aligned.m16n8k16.row.col.f32.bf16.bf16.f32 " \
        "{%0,%1,%2,%3}, {%4,%5,%6,%7}, {%8,%9}, {%0,%1,%2,%3};" \
        : "+f"((c)[0]), "+f"((c)[1]), "+f"((c)[2]), "+f"((c)[3]) \
        : "r"((a)[0]), "r"((a)[1]), "r"((a)[2]), "r"((a)[3]), "r"(b0), "r"(b1))

// split a pair of floats into packed bf16x2 hi and lo words
__device__ __forceinline__ void split2(float a, float b, uint32_t& hi, uint32_t& lo) {
    __nv_bfloat16 ha = __float2bfloat16_rn(a);
    __nv_bfloat16 hb = __float2bfloat16_rn(b);
    hi = (uint32_t)__bfloat16_as_ushort(ha) | ((uint32_t)__bfloat16_as_ushort(hb) << 16);
    __nv_bfloat162 l = __floats2bfloat162_rn(a - __bfloat162float(ha),
                                             b - __bfloat162float(hb));
    lo = *reinterpret_cast<uint32_t*>(&l);
}

// ===========================================================================
// f32 -> bf16 hi/lo split (elementwise; used for x and W)
// ===========================================================================
__global__ __launch_bounds__(256) void split_bf16_kernel(
    const float* __restrict__ src, __nv_bfloat16* __restrict__ hi,
    __nv_bfloat16* __restrict__ lo, int n4)
{
    int i = blockIdx.x * blockDim.x + threadIdx.x;
    if (i >= n4) return;
    float4 v = reinterpret_cast<const float4*>(src)[i];
    uint32_t h0, l0, h1, l1;
    split2(v.x, v.y, h0, l0);
    split2(v.z, v.w, h1, l1);
    uint2 hv = { h0, h1 }, lv = { l0, l1 };
    reinterpret_cast<uint2*>(hi)[i] = hv;
    reinterpret_cast<uint2*>(lo)[i] = lv;
}

// ===========================================================================
// Split-bf16 tensor-core GEMM (unchanged mainloop from R8 WIN):
//   C = Ah@Wh^T + Ah@Wl^T + Al@Wh^T + bias
// Epilogue writes either f32 C, or bf16 hi/lo split (scaled by oscale).
// ===========================================================================
#define GM 128
#define GN 128
#define KC 64
#define NCHUNK (HID / KC)     // 32
#define GSTR 72
#define TELEM (128 * GSTR)
#define STAGE_ELEM (4 * TELEM)
#define GEMM_SMEM_B (2 * STAGE_ELEM * 2)

__global__ __launch_bounds__(256) void gemm_mma(
    const __nv_bfloat16* __restrict__ Ah, const __nv_bfloat16* __restrict__ Al,
    const __nv_bfloat16* __restrict__ Wh, const __nv_bfloat16* __restrict__ Wl,
    const float* __restrict__ bias, float* __restrict__ C,
    __nv_bfloat16* __restrict__ Ch, __nv_bfloat16* __restrict__ Cl,
    float oscale, int M, int N, int K)
{
    extern __shared__ __nv_bfloat16 sm[];
    const int tid  = threadIdx.x;
    const int lane = tid & 31;
    const int wid  = tid >> 5;
    const int warp_m = wid >> 2;
    const int warp_n = wid & 3;
    const int m0 = blockIdx.y * GM;
    const int n0 = blockIdx.x * GN;

    const uint32_t smb = smem_u32(sm);

    float acc[4][4][4];
    #pragma unroll
    for (int a = 0; a < 4; ++a)
        #pragma unroll
        for (int b = 0; b < 4; ++b)
            #pragma unroll
            for (int c = 0; c < 4; ++c) acc[a][b][c] = 0.0f;

    int lrow[4], lcol[4];
    #pragma unroll
    for (int i = 0; i < 4; ++i) {
        int linear = tid + i * 256;
        lrow[i] = linear >> 3;
        lcol[i] = (linear & 7) * 8;
    }

    auto load_chunk = [&](int ck, int s) {
        const int k0 = ck * KC;
        uint32_t stage_b = smb + (uint32_t)s * STAGE_ELEM * 2;
        const __nv_bfloat16* gsrc[4] = {
            Ah + (size_t)m0 * K + k0, Al + (size_t)m0 * K + k0,
            Wh + (size_t)n0 * K + k0, Wl + (size_t)n0 * K + k0 };
        #pragma unroll
        for (int t = 0; t < 4; ++t) {
            uint32_t tb = stage_b + (uint32_t)t * TELEM * 2;
            #pragma unroll
            for (int i = 0; i < 4; ++i) {
                uint32_t dst = tb + (uint32_t)(lrow[i] * GSTR + lcol[i]) * 2;
                const __nv_bfloat16* src = gsrc[t] + (size_t)lrow[i] * K + lcol[i];
                CP_ASYNC16(dst, src);
            }
        }
    };

    load_chunk(0, 0); CP_COMMIT();
    load_chunk(1, 1); CP_COMMIT();

    const int arow  = warp_m * 64 + (lane & 15);
    const int aksel = (lane >> 4) << 3;
    const int brow  = warp_n * 32 + ((lane >> 4) << 3) + (lane & 7);
    const int bksel = ((lane >> 3) & 1) * 8;

    for (int ck = 0; ck < NCHUNK; ++ck) {
        const int s = ck & 1;
        CP_WAIT1();
        __syncthreads();

        uint32_t stage_b = smb + (uint32_t)s * STAGE_ELEM * 2;
        uint32_t bAh = stage_b;
        uint32_t bAl = stage_b + TELEM * 2;
        uint32_t bWh = stage_b + 2 * TELEM * 2;
        uint32_t bWl = stage_b + 3 * TELEM * 2;

        #pragma unroll
        for (int ks = 0; ks < KC / 16; ++ks) {
            const int akoff = ks * 16 + aksel;
            const int bkoff = ks * 16 + bksel;

            uint32_t ah[4][4], al[4][4];
            #pragma unroll
            for (int a = 0; a < 4; ++a) {
                uint32_t off = (uint32_t)((arow + a * 16) * GSTR + akoff) * 2;
                LDMATRIX_X4(ah[a][0], ah[a][1], ah[a][2], ah[a][3], bAh + off);
                LDMATRIX_X4(al[a][0], al[a][1], al[a][2], al[a][3], bAl + off);
            }
            uint32_t bh[2][4], bl[2][4];
            #pragma unroll
            for (int p = 0; p < 2; ++p) {
                uint32_t off = (uint32_t)((brow + p * 16) * GSTR + bkoff) * 2;
                LDMATRIX_X4(bh[p][0], bh[p][1], bh[p][2], bh[p][3], bWh + off);
                LDMATRIX_X4(bl[p][0], bl[p][1], bl[p][2], bl[p][3], bWl + off);
            }
            #pragma unroll
            for (int a = 0; a < 4; ++a)
                #pragma unroll
                for (int p = 0; p < 2; ++p)
                    #pragma unroll
                    for (int hq = 0; hq < 2; ++hq) {
                        int nb = p * 2 + hq;
                        MMA_BF16(acc[a][nb], ah[a], bh[p][hq*2], bh[p][hq*2+1]);
                        MMA_BF16(acc[a][nb], ah[a], bl[p][hq*2], bl[p][hq*2+1]);
                        MMA_BF16(acc[a][nb], al[a], bh[p][hq*2], bh[p][hq*2+1]);
                    }
        }
        __syncthreads();
        if (ck + 2 < NCHUNK) load_chunk(ck + 2, s);
        CP_COMMIT();
    }

    // Epilogue
    #pragma unroll
    for (int a = 0; a < 4; ++a) {
        int r_lo = m0 + warp_m * 64 + a * 16 + (lane >> 2);
        #pragma unroll
        for (int nb = 0; nb < 4; ++nb) {
            int c = n0 + warp_n * 32 + nb * 8 + (lane & 3) * 2;
            float b0 = bias[c], b1 = bias[c + 1];
            float y00 = acc[a][nb][0] + b0, y01 = acc[a][nb][1] + b1;
            float y10 = acc[a][nb][2] + b0, y11 = acc[a][nb][3] + b1;
            if (Ch) {
                y00 *= oscale; y01 *= oscale; y10 *= oscale; y11 *= oscale;
                uint32_t h, l;
                split2(y00, y01, h, l);
                *reinterpret_cast<uint32_t*>(Ch + (size_t)r_lo * N + c) = h;
                *reinterpret_cast<uint32_t*>(Cl + (size_t)r_lo * N + c) = l;
                split2(y10, y11, h, l);
                *reinterpret_cast<uint32_t*>(Ch + (size_t)(r_lo + 8) * N + c) = h;
                *reinterpret_cast<uint32_t*>(Cl + (size_t)(r_lo + 8) * N + c) = l;
            } else {
                float2 v0 = { y00, y01 }, v1 = { y10, y11 };
                *reinterpret_cast<float2*>(C + (size_t)r_lo * N + c) = v0;
                *reinterpret_cast<float2*>(C + (size_t)(r_lo + 8) * N + c) = v1;
            }
        }
    }
}

// ===========================================================================
// Tensor-core flash attention (split-bf16, no mask).
// BQ=128 q rows / CTA, 8 warps x 16 rows -> warp-local softmax,
// register-resident P. KV chunks of 64, cp.async double-buffered.
// QK^T and P.V both 3-pass hi/lo split. Scale folded into Q (at Q-GEMM).
// ===========================================================================
#define FA_BQ   128
#define FA_BKV  64
#define FA_STR  136                    // bf16 elems per smem row (272B, %128B==16)
#define FA_KT   (FA_BKV * FA_STR)      // 8704 elems per K/V half tile
#define FA_STAGE (4 * FA_KT)           // kh,kl,vh,vl
#define FA_QT   (FA_BQ * FA_STR)      // 17408 elems per Q half
#define FA_SMEM_B ((2 * FA_STAGE + 2 * FA_QT) * 2)   // 208896 bytes

__global__ __launch_bounds__(256, 1) void flash_mma(
    const __nv_bfloat16* __restrict__ qh, const __nv_bfloat16* __restrict__ ql,
    const __nv_bfloat16* __restrict__ kh, const __nv_bfloat16* __restrict__ kl,
    const __nv_bfloat16* __restrict__ vh, const __nv_bfloat16* __restrict__ vl,
    __nv_bfloat16* __restrict__ oh, __nv_bfloat16* __restrict__ ol)
{
    extern __shared__ __nv_bfloat16 fsm[];
    const int tid  = threadIdx.x;
    const int lane = tid & 31;
    const int wid  = tid >> 5;
    const int q0   = blockIdx.x * FA_BQ;
    const int bh_i = blockIdx.y;
    const int b = bh_i >> 4, h = bh_i & 15;
    const size_t rowbase = (size_t)b * SEQ;      // + row -> global row
    const size_t cbase   = (size_t)h * HD;

    const uint32_t smb  = smem_u32(fsm);
    const uint32_t Qh_b = smb + 2 * FA_STAGE * 2;
    const uint32_t Ql_b = Qh_b + FA_QT * 2;

    // ---- issue Q tile loads (group 0): 128 rows x 16 granules x {hi,lo}
    // 128*16 = 2048 granules per tensor; 256 threads -> 8 iterations.
    #pragma unroll
    for (int i = 0; i < 8; ++i) {
        int g = tid + i * 256;
        int r = g >> 4, c = g & 15;
        size_t src = (rowbase + q0 + r) * HID + cbase + c * 8;
        uint32_t doff = (uint32_t)(r * FA_STR + c * 8) * 2;
        CP_ASYNC16(Qh_b + doff, qh + src);
        CP_ASYNC16(Ql_b + doff, ql + src);
    }
    CP_COMMIT();

    // ---- KV chunk loader: 4 tensors x 64 rows x 16 granules
    auto load_kv = [&](int ck, int s) {
        uint32_t stage_b = smb + (uint32_t)s * FA_STAGE * 2;
        const __nv_bfloat16* gsrc[4] = { kh, kl, vh, vl };
        #pragma unroll
        for (int i = 0; i < 4; ++i) {
            int g = tid + i * 256;
            int r = g >> 4, c = g & 15;
            size_t src = (rowbase + ck * FA_BKV + r) * HID + cbase + c * 8;
            uint32_t doff = (uint32_t)(r * FA_STR + c * 8) * 2;
            #pragma unroll
            for (int t = 0; t < 4; ++t)
                CP_ASYNC16(stage_b + (uint32_t)t * FA_KT * 2 + doff, gsrc[t] + src);
        }
    };
    load_kv(0, 0); CP_COMMIT();
    load_kv(1, 1); CP_COMMIT();

    // ---- Q fragments (hi resident in registers; lo re-loaded per chunk)
    CP_WAIT2();
    __syncthreads();
    uint32_t qfh[8][4];
    const int arow = wid * 16 + (lane & 15);
    const int aksel = (lane >> 4) << 3;
    #pragma unroll
    for (int ks = 0; ks < 8; ++ks) {
        uint32_t off = (uint32_t)(arow * FA_STR + ks * 16 + aksel) * 2;
        LDMATRIX_X4(qfh[ks][0], qfh[ks][1], qfh[ks][2], qfh[ks][3], Qh_b + off);
    }

    float m0v = -1e30f, m1v = -1e30f, l0 = 0.0f, l1 = 0.0f;
    float acc_o[16][4];
    #pragma unroll
    for (int nf = 0; nf < 16; ++nf)
        #pragma unroll
        for (int c = 0; c < 4; ++c) acc_o[nf][c] = 0.0f;

    const int nrow  = ((lane >> 4) << 3) + (lane & 7);   // K n-row within 16-group
    const int kksel = ((lane >> 3) & 1) * 8;
    const int vrow  = lane & 15;                          // V k-row within 16
    const int vcol8 = (lane >> 4) << 3;

    for (int ck = 0; ck < SEQ / FA_BKV; ++ck) {
        const int s = ck & 1;
        CP_WAIT1();
        __syncthreads();

        uint32_t stage_b = smb + (uint32_t)s * FA_STAGE * 2;
        uint32_t Kh_b = stage_b;
        uint32_t Kl_b = stage_b + FA_KT * 2;
        uint32_t Vh_b = stage_b + 2 * FA_KT * 2;
        uint32_t Vl_b = stage_b + 3 * FA_KT * 2;

        // ---- S = Q K^T (3-pass split), S is 16x64 per warp
        float accs[8][4];
        #pragma unroll
        for (int j = 0; j < 8; ++j)
            #pragma unroll
            for (int c = 0; c < 4; ++c) accs[j][c] = 0.0f;

        #pragma unroll
        for (int ks = 0; ks < 8; ++ks) {
            uint32_t qlo[4];
            {
                uint32_t off = (uint32_t)(arow * FA_STR + ks * 16 + aksel) * 2;
                LDMATRIX_X4(qlo[0], qlo[1], qlo[2], qlo[3], Ql_b + off);
            }
            #pragma unroll
            for (int g4 = 0; g4 < 4; ++g4) {
                uint32_t off = (uint32_t)((g4 * 16 + nrow) * FA_STR + ks * 16 + kksel) * 2;
                uint32_t kbh[4], kbl[4];
                LDMATRIX_X4(kbh[0], kbh[1], kbh[2], kbh[3], Kh_b + off);
                LDMATRIX_X4(kbl[0], kbl[1], kbl[2], kbl[3], Kl_b + off);
                MMA_BF16(accs[g4*2],   qfh[ks], kbh[0], kbh[1]);
                MMA_BF16(accs[g4*2],   qfh[ks], kbl[0], kbl[1]);
                MMA_BF16(accs[g4*2],   qlo,     kbh[0], kbh[1]);
                MMA_BF16(accs[g4*2+1], qfh[ks], kbh[2], kbh[3]);
                MMA_BF16(accs[g4*2+1], qfh[ks], kbl[2], kbl[3]);
                MMA_BF16(accs[g4*2+1], qlo,     kbh[2], kbh[3]);
            }
        }

        // ---- online softmax (warp-local; rows r=lane>>2 and r+8)
        float mx0 = -1e30f, mx1 = -1e30f;
        #pragma unroll
        for (int j = 0; j < 8; ++j) {
            mx0 = fmaxf(mx0, fmaxf(accs[j][0], accs[j][1]));
            mx1 = fmaxf(mx1, fmaxf(accs[j][2], accs[j][3]));
        }
        mx0 = fmaxf(mx0, __shfl_xor_sync(0xffffffffu, mx0, 1));
        mx0 = fmaxf(mx0, __shfl_xor_sync(0xffffffffu, mx0, 2));
        mx1 = fmaxf(mx1, __shfl_xor_sync(0xffffffffu, mx1, 1));
        mx1 = fmaxf(mx1, __shfl_xor_sync(0xffffffffu, mx1, 2));

        float mn0 = fmaxf(m0v, mx0), mn1 = fmaxf(m1v, mx1);
        float corr0 = __expf(m0v - mn0), corr1 = __expf(m1v - mn1);
        m0v = mn0; m1v = mn1;

        float sum0 = 0.0f, sum1 = 0.0f;
        #pragma unroll
        for (int j = 0; j < 8; ++j) {
            accs[j][0] = __expf(accs[j][0] - mn0);
            accs[j][1] = __expf(accs[j][1] - mn0);
            accs[j][2] = __expf(accs[j][2] - mn1);
            accs[j][3] = __expf(accs[j][3] - mn1);
            sum0 += accs[j][0] + accs[j][1];
            sum1 += accs[j][2] + accs[j][3];
        }
        sum0 += __shfl_xor_sync(0xffffffffu, sum0, 1);
        sum0 += __shfl_xor_sync(0xffffffffu, sum0, 2);
        sum1 += __shfl_xor_sync(0xffffffffu, sum1, 1);
        sum1 += __shfl_xor_sync(0xffffffffu, sum1, 2);
        l0 = l0 * corr0 + sum0;
        l1 = l1 * corr1 + sum1;

        #pragma unroll
        for (int nf = 0; nf < 16; ++nf) {
            acc_o[nf][0] *= corr0; acc_o[nf][1] *= corr0;
            acc_o[nf][2] *= corr1; acc_o[nf][3] *= corr1;
        }

        // ---- P fragments from registers (hi/lo split)
        uint32_t pfh[4][4], pfl[4][4];
        #pragma unroll
        for (int t = 0; t < 4; ++t) {
            int j0 = 2 * t, j1 = 2 * t + 1;
            split2(accs[j0][0], accs[j0][1], pfh[t][0], pfl[t][0]);
            split2(accs[j0][2], accs[j0][3], pfh[t][1], pfl[t][1]);
            split2(accs[j1][0], accs[j1][1], pfh[t][2], pfl[t][2]);
            split2(accs[j1][2], accs[j1][3], pfh[t][3], pfl[t][3]);
        }

        // ---- O += P V (3-pass split); V via ldmatrix.trans
        #pragma unroll
        for (int t = 0; t < 4; ++t) {
            #pragma unroll
            for (int g8 = 0; g8 < 8; ++g8) {
                uint32_t off = (uint32_t)((t * 16 + vrow) * FA_STR + g8 * 16 + vcol8) * 2;
                uint32_t vbh[4], vbl[4];
                LDMATRIX_X4_T(vbh[0], vbh[1], vbh[2], vbh[3], Vh_b + off);
                LDMATRIX_X4_T(vbl[0], vbl[1], vbl[2], vbl[3], Vl_b + off);
                int nf0 = g8 * 2, nf1 = nf0 + 1;
                MMA_BF16(acc_o[nf0], pfh[t], vbh[0], vbh[1]);
                MMA_BF16(acc_o[nf0], pfh[t], vbl[0], vbl[1]);
                MMA_BF16(acc_o[nf0], pfl[t], vbh[0], vbh[1]);
                MMA_BF16(acc_o[nf1], pfh[t], vbh[2], vbh[3]);
                MMA_BF16(acc_o[nf1], pfh[t], vbl[2], vbl[3]);
                MMA_BF16(acc_o[nf1], pfl[t], vbh[2], vbh[3]);
            }
        }

        __syncthreads();
        if (ck + 2 < SEQ / FA_BKV) load_kv(ck + 2, s);
        CP_COMMIT();
    }

    // ---- epilogue: normalize, split to bf16 hi/lo, store
    float inv0 = 1.0f / l0, inv1 = 1.0f / l1;
    int r0 = q0 + wid * 16 + (lane >> 2);
    int r1 = r0 + 8;
    #pragma unroll
    for (int g8 = 0; g8 < 8; ++g8) {
        #pragma unroll
        for (int half = 0; half < 2; ++half) {
            int nf = g8 * 2 + half;
            int c = g8 * 16 + half * 8 + (lane & 3) * 2;
            size_t o0 = (rowbase + r0) * HID + cbase + c;
            size_t o1 = (rowbase + r1) * HID + cbase + c;
            uint32_t hw, lw;
            split2(acc_o[nf][0] * inv0, acc_o[nf][1] * inv0, hw, lw);
            *reinterpret_cast<uint32_t*>(oh + o0) = hw;
            *reinterpret_cast<uint32_t*>(ol + o0) = lw;
            split2(acc_o[nf][2] * inv1, acc_o[nf][3] * inv1, hw, lw);
            *reinterpret_cast<uint32_t*>(oh + o1) = hw;
            *reinterpret_cast<uint32_t*>(ol + o1) = lw;
        }
    }
}

// ---------------------------------------------------------------------------
// Launch
// ---------------------------------------------------------------------------
extern "C" void kernel_launch(void* const* d_in, const int* in_sizes, int n_in,
                              void* d_out, int out_size)
{
    const float* x  = (const float*)d_in[0];
    const float* Wq = (const float*)d_in[1];
    const float* bq = (const float*)d_in[2];
    const float* Wk = (const float*)d_in[3];
    const float* bk = (const float*)d_in[4];
    const float* Wv = (const float*)d_in[5];
    const float* bv = (const float*)d_in[6];
    const float* Wo = (const float*)d_in[7];
    const float* bo = (const float*)d_in[8];
    float* out = (float*)d_out;

    __nv_bfloat16 *xh, *xl, *qh, *ql, *kh, *kl, *vh, *vl, *ah, *al, *Whb, *Wlb;
    cudaGetSymbolAddress((void**)&xh, g_xh);
    cudaGetSymbolAddress((void**)&xl, g_xl);
    cudaGetSymbolAddress((void**)&qh, g_qh);
    cudaGetSymbolAddress((void**)&ql, g_ql);
    cudaGetSymbolAddress((void**)&kh, g_kh);
    cudaGetSymbolAddress((void**)&kl, g_kl);
    cudaGetSymbolAddress((void**)&vh, g_vh);
    cudaGetSymbolAddress((void**)&vl, g_vl);
    cudaGetSymbolAddress((void**)&ah, g_ah);
    cudaGetSymbolAddress((void**)&al, g_al);
    cudaGetSymbolAddress((void**)&Whb, g_Wh);
    cudaGetSymbolAddress((void**)&Wlb, g_Wl);

    cudaFuncSetAttribute(gemm_mma,
                         cudaFuncAttributeMaxDynamicSharedMemorySize, GEMM_SMEM_B);
    cudaFuncSetAttribute(flash_mma,
                         cudaFuncAttributeMaxDynamicSharedMemorySize, FA_SMEM_B);

    // Splits of x and the 4 weight matrices
    const int n4x = (int)(MSZ / 4), n4w = (int)(WSZ / 4);
    split_bf16_kernel<<<(n4x + 255) / 256, 256>>>(x, xh, xl, n4x);
    const float* Ws[4] = { Wq, Wk, Wv, Wo };
    for (int i = 0; i < 4; ++i)
        split_bf16_kernel<<<(n4w + 255) / 256, 256>>>(
            Ws[i], Whb + (size_t)i * WSZ, Wlb + (size_t)i * WSZ, n4w);

    const float scale = 1.0f / sqrtf((float)HD);
    dim3 ggrid(HID / GN, MROWS / GM);   // (16, 32)
    // Q/K/V projections -> split bf16 outputs (Q pre-scaled)
    gemm_mma<<<ggrid, 256, GEMM_SMEM_B>>>(xh, xl, Whb + 0 * WSZ, Wlb + 0 * WSZ,
        bq, nullptr, qh, ql, scale, MROWS, HID, HID);
    gemm_mma<<<ggrid, 256, GEMM_SMEM_B>>>(xh, xl, Whb + 1 * WSZ, Wlb + 1 * WSZ,
        bk, nullptr, kh, kl, 1.0f, MROWS, HID, HID);
    gemm_mma<<<ggrid, 256, GEMM_SMEM_B>>>(xh, xl, Whb + 2 * WSZ, Wlb + 2 * WSZ,
        bv, nullptr, vh, vl, 1.0f, MROWS, HID, HID);

    dim3 fgrid(SEQ / FA_BQ, BATCH * HEADS);  // (16, 32)
    flash_mma<<<fgrid, 256, FA_SMEM_B>>>(qh, ql, kh, kl, vh, vl, ah, al);

    // Output projection -> f32 result
    gemm_mma<<<ggrid, 256, GEMM_SMEM_B>>>(ah, al, Whb + 3 * WSZ, Wlb + 3 * WSZ,
        bo, out, nullptr, nullptr, 1.0f, MROWS, HID, HID);
}

// round 13
// speedup vs baseline: 2.4189x; 1.0318x over previous
#include <cuda_runtime.h>
#include <cuda_bf16.h>
#include <math.h>
#include <stdint.h>

// Problem constants
#define BATCH   2
#define SEQ     2048
#define HID     2048
#define HEADS   16
#define HD      128
#define MROWS   (BATCH * SEQ)          // 4096
#define MSZ     ((size_t)MROWS * HID)  // 8M elements
#define WSZ     ((size_t)HID * HID)    // 4M elements

// bf16 hi/lo split scratch
__device__ __nv_bfloat16 g_xh[MSZ], g_xl[MSZ];
__device__ __nv_bfloat16 g_qh[MSZ], g_ql[MSZ];
__device__ __nv_bfloat16 g_kh[MSZ], g_kl[MSZ];
__device__ __nv_bfloat16 g_vh[MSZ], g_vl[MSZ];
__device__ __nv_bfloat16 g_ah[MSZ], g_al[MSZ];
__device__ __nv_bfloat16 g_Wh[4][WSZ], g_Wl[4][WSZ];

// ===========================================================================
// Helpers
// ===========================================================================
__device__ __forceinline__ uint32_t smem_u32(const void* p) {
    uint32_t a;
    asm("{ .reg .u64 t; cvta.to.shared.u64 t, %1; cvt.u32.u64 %0, t; }"
        : "=r"(a) : "l"(p));
    return a;
}

#define CP_ASYNC16(dst, src) \
    asm volatile("cp.async.cg.shared.global [%0], [%1], 16;" \
        :: "r"(dst), "l"(src))
#define CP_COMMIT() asm volatile("cp.async.commit_group;" ::: "memory")
#define CP_WAIT1()  asm volatile("cp.async.wait_group 1;" ::: "memory")
#define CP_WAIT2()  asm volatile("cp.async.wait_group 2;" ::: "memory")

#define LDMATRIX_X4(r0, r1, r2, r3, addr) \
    asm volatile("ldmatrix.sync.aligned.m8n8.x4.shared.b16 {%0,%1,%2,%3}, [%4];" \
        : "=r"(r0), "=r"(r1), "=r"(r2), "=r"(r3) : "r"(addr))

#define LDMATRIX_X4_T(r0, r1, r2, r3, addr) \
    asm volatile("ldmatrix.sync.aligned.m8n8.x4.trans.shared.b16 {%0,%1,%2,%3}, [%4];" \
        : "=r"(r0), "=r"(r1), "=r"(r2), "=r"(r3) : "r"(addr))

#define MMA_BF16(c, a, b0, b1) \
    asm volatile("mma.sync.aligned.m16n8k16.row.col.f32.bf16.bf16.f32 " \
        "{%0,%1,%2,%3}, {%4,%5,%6,%7}, {%8,%9}, {%0,%1,%2,%3};" \
        : "+f"((c)[0]), "+f"((c)[1]), "+f"((c)[2]), "+f"((c)[3]) \
        : "r"((a)[0]), "r"((a)[1]), "r"((a)[2]), "r"((a)[3]), "r"(b0), "r"(b1))

// split a pair of floats into packed bf16x2 hi and lo words
__device__ __forceinline__ void split2(float a, float b, uint32_t& hi, uint32_t& lo) {
    __nv_bfloat16 ha = __float2bfloat16_rn(a);
    __nv_bfloat16 hb = __float2bfloat16_rn(b);
    hi = (uint32_t)__bfloat16_as_ushort(ha) | ((uint32_t)__bfloat16_as_ushort(hb) << 16);
    __nv_bfloat162 l = __floats2bfloat162_rn(a - __bfloat162float(ha),
                                             b - __bfloat162float(hb));
    lo = *reinterpret_cast<uint32_t*>(&l);
}

// ===========================================================================
// f32 -> bf16 hi/lo split (elementwise; used for x and W)
// ===========================================================================
__global__ __launch_bounds__(256) void split_bf16_kernel(
    const float* __restrict__ src, __nv_bfloat16* __restrict__ hi,
    __nv_bfloat16* __restrict__ lo, int n4)
{
    int i = blockIdx.x * blockDim.x + threadIdx.x;
    if (i >= n4) return;
    float4 v = reinterpret_cast<const float4*>(src)[i];
    uint32_t h0, l0, h1, l1;
    split2(v.x, v.y, h0, l0);
    split2(v.z, v.w, h1, l1);
    uint2 hv = { h0, h1 }, lv = { l0, l1 };
    reinterpret_cast<uint2*>(hi)[i] = hv;
    reinterpret_cast<uint2*>(lo)[i] = lv;
}

// ===========================================================================
// Split-bf16 tensor-core GEMM, 3-stage cp.async pipeline, fused multi-W:
//   C = Ah@W^T(+split terms) + bias ; blockIdx.x>>4 selects W/bias/output.
// One barrier per K-chunk; loads for ck+2 issued before compute of ck.
// ===========================================================================
#define GM 128
#define GN 128
#define KC 64
#define NCHUNK (HID / KC)     // 32
#define GSTR 72
#define TELEM (128 * GSTR)
#define STAGE_ELEM (4 * TELEM)
#define NSTAGE 3
#define GEMM_SMEM_B (NSTAGE * STAGE_ELEM * 2)   // 221184 bytes

__global__ __launch_bounds__(256) void gemm_mma(
    const __nv_bfloat16* __restrict__ Ah, const __nv_bfloat16* __restrict__ Al,
    const __nv_bfloat16* __restrict__ WhB, const __nv_bfloat16* __restrict__ WlB,
    const float* __restrict__ bias0, const float* __restrict__ bias1,
    const float* __restrict__ bias2,
    float* __restrict__ C,
    __nv_bfloat16* __restrict__ Ch0, __nv_bfloat16* __restrict__ Cl0,
    __nv_bfloat16* __restrict__ Ch1, __nv_bfloat16* __restrict__ Cl1,
    __nv_bfloat16* __restrict__ Ch2, __nv_bfloat16* __restrict__ Cl2,
    float oscale0, int M, int N, int K)
{
    extern __shared__ __nv_bfloat16 sm[];
    const int tid  = threadIdx.x;
    const int lane = tid & 31;
    const int wid  = tid >> 5;
    const int warp_m = wid >> 2;
    const int warp_n = wid & 3;
    const int which = blockIdx.x >> 4;               // 0..2 matrix selector
    const int n0 = (blockIdx.x & 15) * GN;
    const int m0 = blockIdx.y * GM;

    const __nv_bfloat16* Wh = WhB + (size_t)which * WSZ;
    const __nv_bfloat16* Wl = WlB + (size_t)which * WSZ;
    const float* bias = (which == 0) ? bias0 : (which == 1) ? bias1 : bias2;
    __nv_bfloat16* Ch = (which == 0) ? Ch0 : (which == 1) ? Ch1 : Ch2;
    __nv_bfloat16* Cl = (which == 0) ? Cl0 : (which == 1) ? Cl1 : Cl2;
    const float oscale = (which == 0) ? oscale0 : 1.0f;

    const uint32_t smb = smem_u32(sm);

    float acc[4][4][4];
    #pragma unroll
    for (int a = 0; a < 4; ++a)
        #pragma unroll
        for (int b = 0; b < 4; ++b)
            #pragma unroll
            for (int c = 0; c < 4; ++c) acc[a][b][c] = 0.0f;

    int lrow[4], lcol[4];
    #pragma unroll
    for (int i = 0; i < 4; ++i) {
        int linear = tid + i * 256;
        lrow[i] = linear >> 3;
        lcol[i] = (linear & 7) * 8;
    }

    auto load_chunk = [&](int ck, int s) {
        const int k0 = ck * KC;
        uint32_t stage_b = smb + (uint32_t)s * STAGE_ELEM * 2;
        const __nv_bfloat16* gsrc[4] = {
            Ah + (size_t)m0 * K + k0, Al + (size_t)m0 * K + k0,
            Wh + (size_t)n0 * K + k0, Wl + (size_t)n0 * K + k0 };
        #pragma unroll
        for (int t = 0; t < 4; ++t) {
            uint32_t tb = stage_b + (uint32_t)t * TELEM * 2;
            #pragma unroll
            for (int i = 0; i < 4; ++i) {
                uint32_t dst = tb + (uint32_t)(lrow[i] * GSTR + lcol[i]) * 2;
                const __nv_bfloat16* src = gsrc[t] + (size_t)lrow[i] * K + lcol[i];
                CP_ASYNC16(dst, src);
            }
        }
    };

    load_chunk(0, 0); CP_COMMIT();
    load_chunk(1, 1); CP_COMMIT();

    const int arow  = warp_m * 64 + (lane & 15);
    const int aksel = (lane >> 4) << 3;
    const int brow  = warp_n * 32 + ((lane >> 4) << 3) + (lane & 7);
    const int bksel = ((lane >> 3) & 1) * 8;

    int s_next = 2;   // stage to fill with chunk ck+2 at iter ck
    for (int ck = 0; ck < NCHUNK; ++ck) {
        const int s = (ck < NSTAGE) ? ck : (ck % NSTAGE);
        CP_WAIT1();
        __syncthreads();

        // Issue loads for ck+2 into the stage freed by chunk ck-1
        if (ck + 2 < NCHUNK) load_chunk(ck + 2, s_next);
        CP_COMMIT();
        s_next = (s_next + 1 == NSTAGE) ? 0 : s_next + 1;

        uint32_t stage_b = smb + (uint32_t)s * STAGE_ELEM * 2;
        uint32_t bAh = stage_b;
        uint32_t bAl = stage_b + TELEM * 2;
        uint32_t bWh = stage_b + 2 * TELEM * 2;
        uint32_t bWl = stage_b + 3 * TELEM * 2;

        #pragma unroll
        for (int ks = 0; ks < KC / 16; ++ks) {
            const int akoff = ks * 16 + aksel;
            const int bkoff = ks * 16 + bksel;

            uint32_t ah[4][4], al[4][4];
            #pragma unroll
            for (int a = 0; a < 4; ++a) {
                uint32_t off = (uint32_t)((arow + a * 16) * GSTR + akoff) * 2;
                LDMATRIX_X4(ah[a][0], ah[a][1], ah[a][2], ah[a][3], bAh + off);
                LDMATRIX_X4(al[a][0], al[a][1], al[a][2], al[a][3], bAl + off);
            }
            uint32_t bh[2][4], bl[2][4];
            #pragma unroll
            for (int p = 0; p < 2; ++p) {
                uint32_t off = (uint32_t)((brow + p * 16) * GSTR + bkoff) * 2;
                LDMATRIX_X4(bh[p][0], bh[p][1], bh[p][2], bh[p][3], bWh + off);
                LDMATRIX_X4(bl[p][0], bl[p][1], bl[p][2], bl[p][3], bWl + off);
            }
            #pragma unroll
            for (int a = 0; a < 4; ++a)
                #pragma unroll
                for (int p = 0; p < 2; ++p)
                    #pragma unroll
                    for (int hq = 0; hq < 2; ++hq) {
                        int nb = p * 2 + hq;
                        MMA_BF16(acc[a][nb], ah[a], bh[p][hq*2], bh[p][hq*2+1]);
                        MMA_BF16(acc[a][nb], ah[a], bl[p][hq*2], bl[p][hq*2+1]);
                        MMA_BF16(acc[a][nb], al[a], bh[p][hq*2], bh[p][hq*2+1]);
                    }
        }
        // no tail barrier: next iteration's top sync covers stage reuse
    }

    // Epilogue
    #pragma unroll
    for (int a = 0; a < 4; ++a) {
        int r_lo = m0 + warp_m * 64 + a * 16 + (lane >> 2);
        #pragma unroll
        for (int nb = 0; nb < 4; ++nb) {
            int c = n0 + warp_n * 32 + nb * 8 + (lane & 3) * 2;
            float b0 = bias[c], b1 = bias[c + 1];
            float y00 = acc[a][nb][0] + b0, y01 = acc[a][nb][1] + b1;
            float y10 = acc[a][nb][2] + b0, y11 = acc[a][nb][3] + b1;
            if (Ch) {
                y00 *= oscale; y01 *= oscale; y10 *= oscale; y11 *= oscale;
                uint32_t h, l;
                split2(y00, y01, h, l);
                *reinterpret_cast<uint32_t*>(Ch + (size_t)r_lo * N + c) = h;
                *reinterpret_cast<uint32_t*>(Cl + (size_t)r_lo * N + c) = l;
                split2(y10, y11, h, l);
                *reinterpret_cast<uint32_t*>(Ch + (size_t)(r_lo + 8) * N + c) = h;
                *reinterpret_cast<uint32_t*>(Cl + (size_t)(r_lo + 8) * N + c) = l;
            } else {
                float2 v0 = { y00, y01 }, v1 = { y10, y11 };
                *reinterpret_cast<float2*>(C + (size_t)r_lo * N + c) = v0;
                *reinterpret_cast<float2*>(C + (size_t)(r_lo + 8) * N + c) = v1;
            }
        }
    }
}

// ===========================================================================
// Tensor-core flash attention (split-bf16, no mask) — unchanged from R12 WIN.
// ===========================================================================
#define FA_BQ   128
#define FA_BKV  64
#define FA_STR  136                    // bf16 elems per smem row (272B, %128B==16)
#define FA_KT   (FA_BKV * FA_STR)      // 8704 elems per K/V half tile
#define FA_STAGE (4 * FA_KT)           // kh,kl,vh,vl
#define FA_QT   (FA_BQ * FA_STR)      // 17408 elems per Q half
#define FA_SMEM_B ((2 * FA_STAGE + 2 * FA_QT) * 2)   // 208896 bytes

__global__ __launch_bounds__(256, 1) void flash_mma(
    const __nv_bfloat16* __restrict__ qh, const __nv_bfloat16* __restrict__ ql,
    const __nv_bfloat16* __restrict__ kh, const __nv_bfloat16* __restrict__ kl,
    const __nv_bfloat16* __restrict__ vh, const __nv_bfloat16* __restrict__ vl,
    __nv_bfloat16* __restrict__ oh, __nv_bfloat16* __restrict__ ol)
{
    extern __shared__ __nv_bfloat16 fsm[];
    const int tid  = threadIdx.x;
    const int lane = tid & 31;
    const int wid  = tid >> 5;
    const int q0   = blockIdx.x * FA_BQ;
    const int bh_i = blockIdx.y;
    const int b = bh_i >> 4, h = bh_i & 15;
    const size_t rowbase = (size_t)b * SEQ;      // + row -> global row
    const size_t cbase   = (size_t)h * HD;

    const uint32_t smb  = smem_u32(fsm);
    const uint32_t Qh_b = smb + 2 * FA_STAGE * 2;
    const uint32_t Ql_b = Qh_b + FA_QT * 2;

    // ---- issue Q tile loads (group 0): 128 rows x 16 granules x {hi,lo}
    // 128*16 = 2048 granules per tensor; 256 threads -> 8 iterations.
    #pragma unroll
    for (int i = 0; i < 8; ++i) {
        int g = tid + i * 256;
        int r = g >> 4, c = g & 15;
        size_t src = (rowbase + q0 + r) * HID + cbase + c * 8;
        uint32_t doff = (uint32_t)(r * FA_STR + c * 8) * 2;
        CP_ASYNC16(Qh_b + doff, qh + src);
        CP_ASYNC16(Ql_b + doff, ql + src);
    }
    CP_COMMIT();

    // ---- KV chunk loader: 4 tensors x 64 rows x 16 granules
    auto load_kv = [&](int ck, int s) {
        uint32_t stage_b = smb + (uint32_t)s * FA_STAGE * 2;
        const __nv_bfloat16* gsrc[4] = { kh, kl, vh, vl };
        #pragma unroll
        for (int i = 0; i < 4; ++i) {
            int g = tid + i * 256;
            int r = g >> 4, c = g & 15;
            size_t src = (rowbase + ck * FA_BKV + r) * HID + cbase + c * 8;
            uint32_t doff = (uint32_t)(r * FA_STR + c * 8) * 2;
            #pragma unroll
            for (int t = 0; t < 4; ++t)
                CP_ASYNC16(stage_b + (uint32_t)t * FA_KT * 2 + doff, gsrc[t] + src);
        }
    };
    load_kv(0, 0); CP_COMMIT();
    load_kv(1, 1); CP_COMMIT();

    // ---- Q fragments (hi resident in registers; lo re-loaded per chunk)
    CP_WAIT2();
    __syncthreads();
    uint32_t qfh[8][4];
    const int arow = wid * 16 + (lane & 15);
    const int aksel = (lane >> 4) << 3;
    #pragma unroll
    for (int ks = 0; ks < 8; ++ks) {
        uint32_t off = (uint32_t)(arow * FA_STR + ks * 16 + aksel) * 2;
        LDMATRIX_X4(qfh[ks][0], qfh[ks][1], qfh[ks][2], qfh[ks][3], Qh_b + off);
    }

    float m0v = -1e30f, m1v = -1e30f, l0 = 0.0f, l1 = 0.0f;
    float acc_o[16][4];
    #pragma unroll
    for (int nf = 0; nf < 16; ++nf)
        #pragma unroll
        for (int c = 0; c < 4; ++c) acc_o[nf][c] = 0.0f;

    const int nrow  = ((lane >> 4) << 3) + (lane & 7);   // K n-row within 16-group
    const int kksel = ((lane >> 3) & 1) * 8;
    const int vrow  = lane & 15;                          // V k-row within 16
    const int vcol8 = (lane >> 4) << 3;

    for (int ck = 0; ck < SEQ / FA_BKV; ++ck) {
        const int s = ck & 1;
        CP_WAIT1();
        __syncthreads();

        uint32_t stage_b = smb + (uint32_t)s * FA_STAGE * 2;
        uint32_t Kh_b = stage_b;
        uint32_t Kl_b = stage_b + FA_KT * 2;
        uint32_t Vh_b = stage_b + 2 * FA_KT * 2;
        uint32_t Vl_b = stage_b + 3 * FA_KT * 2;

        // ---- S = Q K^T (3-pass split), S is 16x64 per warp
        float accs[8][4];
        #pragma unroll
        for (int j = 0; j < 8; ++j)
            #pragma unroll
            for (int c = 0; c < 4; ++c) accs[j][c] = 0.0f;

        #pragma unroll
        for (int ks = 0; ks < 8; ++ks) {
            uint32_t qlo[4];
            {
                uint32_t off = (uint32_t)(arow * FA_STR + ks * 16 + aksel) * 2;
                LDMATRIX_X4(qlo[0], qlo[1], qlo[2], qlo[3], Ql_b + off);
            }
            #pragma unroll
            for (int g4 = 0; g4 < 4; ++g4) {
                uint32_t off = (uint32_t)((g4 * 16 + nrow) * FA_STR + ks * 16 + kksel) * 2;
                uint32_t kbh[4], kbl[4];
                LDMATRIX_X4(kbh[0], kbh[1], kbh[2], kbh[3], Kh_b + off);
                LDMATRIX_X4(kbl[0], kbl[1], kbl[2], kbl[3], Kl_b + off);
                MMA_BF16(accs[g4*2],   qfh[ks], kbh[0], kbh[1]);
                MMA_BF16(accs[g4*2],   qfh[ks], kbl[0], kbl[1]);
                MMA_BF16(accs[g4*2],   qlo,     kbh[0], kbh[1]);
                MMA_BF16(accs[g4*2+1], qfh[ks], kbh[2], kbh[3]);
                MMA_BF16(accs[g4*2+1], qfh[ks], kbl[2], kbl[3]);
                MMA_BF16(accs[g4*2+1], qlo,     kbh[2], kbh[3]);
            }
        }

        // ---- online softmax (warp-local; rows r=lane>>2 and r+8)
        float mx0 = -1e30f, mx1 = -1e30f;
        #pragma unroll
        for (int j = 0; j < 8; ++j) {
            mx0 = fmaxf(mx0, fmaxf(accs[j][0], accs[j][1]));
            mx1 = fmaxf(mx1, fmaxf(accs[j][2], accs[j][3]));
        }
        mx0 = fmaxf(mx0, __shfl_xor_sync(0xffffffffu, mx0, 1));
        mx0 = fmaxf(mx0, __shfl_xor_sync(0xffffffffu, mx0, 2));
        mx1 = fmaxf(mx1, __shfl_xor_sync(0xffffffffu, mx1, 1));
        mx1 = fmaxf(mx1, __shfl_xor_sync(0xffffffffu, mx1, 2));

        float mn0 = fmaxf(m0v, mx0), mn1 = fmaxf(m1v, mx1);
        float corr0 = __expf(m0v - mn0), corr1 = __expf(m1v - mn1);
        m0v = mn0; m1v = mn1;

        float sum0 = 0.0f, sum1 = 0.0f;
        #pragma unroll
        for (int j = 0; j < 8; ++j) {
            accs[j][0] = __expf(accs[j][0] - mn0);
            accs[j][1] = __expf(accs[j][1] - mn0);
            accs[j][2] = __expf(accs[j][2] - mn1);
            accs[j][3] = __expf(accs[j][3] - mn1);
            sum0 += accs[j][0] + accs[j][1];
            sum1 += accs[j][2] + accs[j][3];
        }
        sum0 += __shfl_xor_sync(0xffffffffu, sum0, 1);
        sum0 += __shfl_xor_sync(0xffffffffu, sum0, 2);
        sum1 += __shfl_xor_sync(0xffffffffu, sum1, 1);
        sum1 += __shfl_xor_sync(0xffffffffu, sum1, 2);
        l0 = l0 * corr0 + sum0;
        l1 = l1 * corr1 + sum1;

        #pragma unroll
        for (int nf = 0; nf < 16; ++nf) {
            acc_o[nf][0] *= corr0; acc_o[nf][1] *= corr0;
            acc_o[nf][2] *= corr1; acc_o[nf][3] *= corr1;
        }

        // ---- P fragments from registers (hi/lo split)
        uint32_t pfh[4][4], pfl[4][4];
        #pragma unroll
        for (int t = 0; t < 4; ++t) {
            int j0 = 2 * t, j1 = 2 * t + 1;
            split2(accs[j0][0], accs[j0][1], pfh[t][0], pfl[t][0]);
            split2(accs[j0][2], accs[j0][3], pfh[t][1], pfl[t][1]);
            split2(accs[j1][0], accs[j1][1], pfh[t][2], pfl[t][2]);
            split2(accs[j1][2], accs[j1][3], pfh[t][3], pfl[t][3]);
        }

        // ---- O += P V (3-pass split); V via ldmatrix.trans
        #pragma unroll
        for (int t = 0; t < 4; ++t) {
            #pragma unroll
            for (int g8 = 0; g8 < 8; ++g8) {
                uint32_t off = (uint32_t)((t * 16 + vrow) * FA_STR + g8 * 16 + vcol8) * 2;
                uint32_t vbh[4], vbl[4];
                LDMATRIX_X4_T(vbh[0], vbh[1], vbh[2], vbh[3], Vh_b + off);
                LDMATRIX_X4_T(vbl[0], vbl[1], vbl[2], vbl[3], Vl_b + off);
                int nf0 = g8 * 2, nf1 = nf0 + 1;
                MMA_BF16(acc_o[nf0], pfh[t], vbh[0], vbh[1]);
                MMA_BF16(acc_o[nf0], pfh[t], vbl[0], vbl[1]);
                MMA_BF16(acc_o[nf0], pfl[t], vbh[0], vbh[1]);
                MMA_BF16(acc_o[nf1], pfh[t], vbh[2], vbh[3]);
                MMA_BF16(acc_o[nf1], pfh[t], vbl[2], vbl[3]);
                MMA_BF16(acc_o[nf1], pfl[t], vbh[2], vbh[3]);
            }
        }

        __syncthreads();
        if (ck + 2 < SEQ / FA_BKV) load_kv(ck + 2, s);
        CP_COMMIT();
    }

    // ---- epilogue: normalize, split to bf16 hi/lo, store
    float inv0 = 1.0f / l0, inv1 = 1.0f / l1;
    int r0 = q0 + wid * 16 + (lane >> 2);
    int r1 = r0 + 8;
    #pragma unroll
    for (int g8 = 0; g8 < 8; ++g8) {
        #pragma unroll
        for (int half = 0; half < 2; ++half) {
            int nf = g8 * 2 + half;
            int c = g8 * 16 + half * 8 + (lane & 3) * 2;
            size_t o0 = (rowbase + r0) * HID + cbase + c;
            size_t o1 = (rowbase + r1) * HID + cbase + c;
            uint32_t hw, lw;
            split2(acc_o[nf][0] * inv0, acc_o[nf][1] * inv0, hw, lw);
            *reinterpret_cast<uint32_t*>(oh + o0) = hw;
            *reinterpret_cast<uint32_t*>(ol + o0) = lw;
            split2(acc_o[nf][2] * inv1, acc_o[nf][3] * inv1, hw, lw);
            *reinterpret_cast<uint32_t*>(oh + o1) = hw;
            *reinterpret_cast<uint32_t*>(ol + o1) = lw;
        }
    }
}

// ---------------------------------------------------------------------------
// Launch
// ---------------------------------------------------------------------------
extern "C" void kernel_launch(void* const* d_in, const int* in_sizes, int n_in,
                              void* d_out, int out_size)
{
    const float* x  = (const float*)d_in[0];
    const float* Wq = (const float*)d_in[1];
    const float* bq = (const float*)d_in[2];
    const float* Wk = (const float*)d_in[3];
    const float* bk = (const float*)d_in[4];
    const float* Wv = (const float*)d_in[5];
    const float* bv = (const float*)d_in[6];
    const float* Wo = (const float*)d_in[7];
    const float* bo = (const float*)d_in[8];
    float* out = (float*)d_out;

    __nv_bfloat16 *xh, *xl, *qh, *ql, *kh, *kl, *vh, *vl, *ah, *al, *Whb, *Wlb;
    cudaGetSymbolAddress((void**)&xh, g_xh);
    cudaGetSymbolAddress((void**)&xl, g_xl);
    cudaGetSymbolAddress((void**)&qh, g_qh);
    cudaGetSymbolAddress((void**)&ql, g_ql);
    cudaGetSymbolAddress((void**)&kh, g_kh);
    cudaGetSymbolAddress((void**)&kl, g_kl);
    cudaGetSymbolAddress((void**)&vh, g_vh);
    cudaGetSymbolAddress((void**)&vl, g_vl);
    cudaGetSymbolAddress((void**)&ah, g_ah);
    cudaGetSymbolAddress((void**)&al, g_al);
    cudaGetSymbolAddress((void**)&Whb, g_Wh);
    cudaGetSymbolAddress((void**)&Wlb, g_Wl);

    cudaFuncSetAttribute(gemm_mma,
                         cudaFuncAttributeMaxDynamicSharedMemorySize, GEMM_SMEM_B);
    cudaFuncSetAttribute(flash_mma,
                         cudaFuncAttributeMaxDynamicSharedMemorySize, FA_SMEM_B);

    // Splits of x and the 4 weight matrices
    const int n4x = (int)(MSZ / 4), n4w = (int)(WSZ / 4);
    split_bf16_kernel<<<(n4x + 255) / 256, 256>>>(x, xh, xl, n4x);
    const float* Ws[4] = { Wq, Wk, Wv, Wo };
    for (int i = 0; i < 4; ++i)
        split_bf16_kernel<<<(n4w + 255) / 256, 256>>>(
            Ws[i], Whb + (size_t)i * WSZ, Wlb + (size_t)i * WSZ, n4w);

    const float scale = 1.0f / sqrtf((float)HD);

    // Fused Q/K/V projections: one launch, which = blockIdx.x>>4
    dim3 qkv_grid(3 * (HID / GN), MROWS / GM);   // (48, 32)
    gemm_mma<<<qkv_grid, 256, GEMM_SMEM_B>>>(
        xh, xl, Whb, Wlb, bq, bk, bv,
        nullptr, qh, ql, kh, kl, vh, vl,
        scale, MROWS, HID, HID);

    dim3 fgrid(SEQ / FA_BQ, BATCH * HEADS);  // (16, 32)
    flash_mma<<<fgrid, 256, FA_SMEM_B>>>(qh, ql, kh, kl, vh, vl, ah, al);

    // Output projection -> f32 result (which=0 only)
    dim3 ogrid(HID / GN, MROWS / GM);   // (16, 32)
    gemm_mma<<<ogrid, 256, GEMM_SMEM_B>>>(
        ah, al, Whb + 3 * WSZ, Wlb + 3 * WSZ, bo, nullptr, nullptr,
        out, nullptr, nullptr, nullptr, nullptr, nullptr, nullptr,
        1.0f, MROWS, HID, HID);
}

// round 14
// speedup vs baseline: 3.1439x; 1.2997x over previous
#include <cuda_runtime.h>
#include <cuda_bf16.h>
#include <cuda_fp16.h>
#include <math.h>
#include <stdint.h>

// Problem constants
#define BATCH   2
#define SEQ     2048
#define HID     2048
#define HEADS   16
#define HD      128
#define MROWS   (BATCH * SEQ)          // 4096
#define MSZ     ((size_t)MROWS * HID)  // 8M elements
#define WSZ     ((size_t)HID * HID)    // 4M elements

// fp16 GEMM operands (A single, W hi/lo)
__device__ __half g_x16[MSZ];
__device__ __half g_a16[MSZ];
__device__ __half g_Wh[4][WSZ], g_Wl[4][WSZ];
// bf16 hi/lo split Q/K/V for flash (3-pass path, unchanged)
__device__ __nv_bfloat16 g_qh[MSZ], g_ql[MSZ];
__device__ __nv_bfloat16 g_kh[MSZ], g_kl[MSZ];
__device__ __nv_bfloat16 g_vh[MSZ], g_vl[MSZ];

// ===========================================================================
// Helpers
// ===========================================================================
__device__ __forceinline__ uint32_t smem_u32(const void* p) {
    uint32_t a;
    asm("{ .reg .u64 t; cvta.to.shared.u64 t, %1; cvt.u32.u64 %0, t; }"
        : "=r"(a) : "l"(p));
    return a;
}

#define CP_ASYNC16(dst, src) \
    asm volatile("cp.async.cg.shared.global [%0], [%1], 16;" \
        :: "r"(dst), "l"(src))
#define CP_COMMIT() asm volatile("cp.async.commit_group;" ::: "memory")
#define CP_WAIT1()  asm volatile("cp.async.wait_group 1;" ::: "memory")
#define CP_WAIT2()  asm volatile("cp.async.wait_group 2;" ::: "memory")

#define LDMATRIX_X4(r0, r1, r2, r3, addr) \
    asm volatile("ldmatrix.sync.aligned.m8n8.x4.shared.b16 {%0,%1,%2,%3}, [%4];" \
        : "=r"(r0), "=r"(r1), "=r"(r2), "=r"(r3) : "r"(addr))

#define LDMATRIX_X4_T(r0, r1, r2, r3, addr) \
    asm volatile("ldmatrix.sync.aligned.m8n8.x4.trans.shared.b16 {%0,%1,%2,%3}, [%4];" \
        : "=r"(r0), "=r"(r1), "=r"(r2), "=r"(r3) : "r"(addr))

#define MMA_BF16(c, a, b0, b1) \
    asm volatile("mma.sync.aligned.m16n8k16.row.col.f32.bf16.bf16.f32 " \
        "{%0,%1,%2,%3}, {%4,%5,%6,%7}, {%8,%9}, {%0,%1,%2,%3};" \
        : "+f"((c)[0]), "+f"((c)[1]), "+f"((c)[2]), "+f"((c)[3]) \
        : "r"((a)[0]), "r"((a)[1]), "r"((a)[2]), "r"((a)[3]), "r"(b0), "r"(b1))

#define MMA_F16(c, a, b0, b1) \
    asm volatile("mma.sync.aligned.m16n8k16.row.col.f32.f16.f16.f32 " \
        "{%0,%1,%2,%3}, {%4,%5,%6,%7}, {%8,%9}, {%0,%1,%2,%3};" \
        : "+f"((c)[0]), "+f"((c)[1]), "+f"((c)[2]), "+f"((c)[3]) \
        : "r"((a)[0]), "r"((a)[1]), "r"((a)[2]), "r"((a)[3]), "r"(b0), "r"(b1))

// split a pair of floats into packed bf16x2 hi and lo words
__device__ __forceinline__ void split2(float a, float b, uint32_t& hi, uint32_t& lo) {
    __nv_bfloat16 ha = __float2bfloat16_rn(a);
    __nv_bfloat16 hb = __float2bfloat16_rn(b);
    hi = (uint32_t)__bfloat16_as_ushort(ha) | ((uint32_t)__bfloat16_as_ushort(hb) << 16);
    __nv_bfloat162 l = __floats2bfloat162_rn(a - __bfloat162float(ha),
                                             b - __bfloat162float(hb));
    lo = *reinterpret_cast<uint32_t*>(&l);
}

// split a pair of floats into packed fp16x2 hi and lo words
__device__ __forceinline__ void split2h(float a, float b, uint32_t& hi, uint32_t& lo) {
    __half ha = __float2half_rn(a);
    __half hb = __float2half_rn(b);
    hi = (uint32_t)__half_as_ushort(ha) | ((uint32_t)__half_as_ushort(hb) << 16);
    __half2 l = __floats2half2_rn(a - __half2float(ha), b - __half2float(hb));
    lo = *reinterpret_cast<uint32_t*>(&l);
}

// ===========================================================================
// Conversion kernels
// ===========================================================================
// f32 -> fp16 hi/lo split (weights)
__global__ __launch_bounds__(256) void split_f16hl_kernel(
    const float* __restrict__ src, __half* __restrict__ hi,
    __half* __restrict__ lo, int n4)
{
    int i = blockIdx.x * blockDim.x + threadIdx.x;
    if (i >= n4) return;
    float4 v = reinterpret_cast<const float4*>(src)[i];
    uint32_t h0, l0, h1, l1;
    split2h(v.x, v.y, h0, l0);
    split2h(v.z, v.w, h1, l1);
    uint2 hv = { h0, h1 }, lv = { l0, l1 };
    reinterpret_cast<uint2*>(hi)[i] = hv;
    reinterpret_cast<uint2*>(lo)[i] = lv;
}

// f32 -> fp16 (activations; single word)
__global__ __launch_bounds__(256) void cvt_f16_kernel(
    const float* __restrict__ src, __half* __restrict__ dst, int n4)
{
    int i = blockIdx.x * blockDim.x + threadIdx.x;
    if (i >= n4) return;
    float4 v = reinterpret_cast<const float4*>(src)[i];
    __half2 a = __floats2half2_rn(v.x, v.y);
    __half2 b = __floats2half2_rn(v.z, v.w);
    uint2 o = { *reinterpret_cast<uint32_t*>(&a), *reinterpret_cast<uint32_t*>(&b) };
    reinterpret_cast<uint2*>(dst)[i] = o;
}

// ===========================================================================
// fp16 2-pass tensor-core GEMM, 3-stage cp.async pipeline, fused multi-W:
//   C = A16 @ Wh^T + A16 @ Wl^T + bias ; blockIdx.x>>4 selects W/bias/output.
// 3 smem tiles per stage (A, Wh, Wl). One barrier per K-chunk.
// ===========================================================================
#define GM 128
#define GN 128
#define KC 64
#define NCHUNK (HID / KC)     // 32
#define GSTR 72
#define TELEM (128 * GSTR)    // 9216 elems per tile
#define STAGE_ELEM (3 * TELEM)
#define NSTAGE 3
#define GEMM_SMEM_B (NSTAGE * STAGE_ELEM * 2)   // 165888 bytes

__global__ __launch_bounds__(256) void gemm_mma(
    const __half* __restrict__ A,
    const __half* __restrict__ WhB, const __half* __restrict__ WlB,
    const float* __restrict__ bias0, const float* __restrict__ bias1,
    const float* __restrict__ bias2,
    float* __restrict__ C,
    __nv_bfloat16* __restrict__ Ch0, __nv_bfloat16* __restrict__ Cl0,
    __nv_bfloat16* __restrict__ Ch1, __nv_bfloat16* __restrict__ Cl1,
    __nv_bfloat16* __restrict__ Ch2, __nv_bfloat16* __restrict__ Cl2,
    float oscale0, int M, int N, int K)
{
    extern __shared__ __half sm[];
    const int tid  = threadIdx.x;
    const int lane = tid & 31;
    const int wid  = tid >> 5;
    const int warp_m = wid >> 2;
    const int warp_n = wid & 3;
    const int which = blockIdx.x >> 4;               // 0..2 matrix selector
    const int n0 = (blockIdx.x & 15) * GN;
    const int m0 = blockIdx.y * GM;

    const __half* Wh = WhB + (size_t)which * WSZ;
    const __half* Wl = WlB + (size_t)which * WSZ;
    const float* bias = (which == 0) ? bias0 : (which == 1) ? bias1 : bias2;
    __nv_bfloat16* Ch = (which == 0) ? Ch0 : (which == 1) ? Ch1 : Ch2;
    __nv_bfloat16* Cl = (which == 0) ? Cl0 : (which == 1) ? Cl1 : Cl2;
    const float oscale = (which == 0) ? oscale0 : 1.0f;

    const uint32_t smb = smem_u32(sm);

    float acc[4][4][4];
    #pragma unroll
    for (int a = 0; a < 4; ++a)
        #pragma unroll
        for (int b = 0; b < 4; ++b)
            #pragma unroll
            for (int c = 0; c < 4; ++c) acc[a][b][c] = 0.0f;

    int lrow[4], lcol[4];
    #pragma unroll
    for (int i = 0; i < 4; ++i) {
        int linear = tid + i * 256;       // 0..1023 granules per tile
        lrow[i] = linear >> 3;
        lcol[i] = (linear & 7) * 8;
    }

    auto load_chunk = [&](int ck, int s) {
        const int k0 = ck * KC;
        uint32_t stage_b = smb + (uint32_t)s * STAGE_ELEM * 2;
        const __half* gsrc[3] = {
            A + (size_t)m0 * K + k0,
            Wh + (size_t)n0 * K + k0, Wl + (size_t)n0 * K + k0 };
        #pragma unroll
        for (int t = 0; t < 3; ++t) {
            uint32_t tb = stage_b + (uint32_t)t * TELEM * 2;
            #pragma unroll
            for (int i = 0; i < 4; ++i) {
                uint32_t dst = tb + (uint32_t)(lrow[i] * GSTR + lcol[i]) * 2;
                const __half* src = gsrc[t] + (size_t)lrow[i] * K + lcol[i];
                CP_ASYNC16(dst, src);
            }
        }
    };

    load_chunk(0, 0); CP_COMMIT();
    load_chunk(1, 1); CP_COMMIT();

    const int arow  = warp_m * 64 + (lane & 15);
    const int aksel = (lane >> 4) << 3;
    const int brow  = warp_n * 32 + ((lane >> 4) << 3) + (lane & 7);
    const int bksel = ((lane >> 3) & 1) * 8;

    int s_next = 2;   // stage to fill with chunk ck+2 at iter ck
    for (int ck = 0; ck < NCHUNK; ++ck) {
        const int s = (ck < NSTAGE) ? ck : (ck % NSTAGE);
        CP_WAIT1();
        __syncthreads();

        if (ck + 2 < NCHUNK) load_chunk(ck + 2, s_next);
        CP_COMMIT();
        s_next = (s_next + 1 == NSTAGE) ? 0 : s_next + 1;

        uint32_t stage_b = smb + (uint32_t)s * STAGE_ELEM * 2;
        uint32_t bA  = stage_b;
        uint32_t bWh = stage_b + TELEM * 2;
        uint32_t bWl = stage_b + 2 * TELEM * 2;

        #pragma unroll
        for (int ks = 0; ks < KC / 16; ++ks) {
            const int akoff = ks * 16 + aksel;
            const int bkoff = ks * 16 + bksel;

            uint32_t af[4][4];
            #pragma unroll
            for (int a = 0; a < 4; ++a) {
                uint32_t off = (uint32_t)((arow + a * 16) * GSTR + akoff) * 2;
                LDMATRIX_X4(af[a][0], af[a][1], af[a][2], af[a][3], bA + off);
            }
            uint32_t bh[2][4], bl[2][4];
            #pragma unroll
            for (int p = 0; p < 2; ++p) {
                uint32_t off = (uint32_t)((brow + p * 16) * GSTR + bkoff) * 2;
                LDMATRIX_X4(bh[p][0], bh[p][1], bh[p][2], bh[p][3], bWh + off);
                LDMATRIX_X4(bl[p][0], bl[p][1], bl[p][2], bl[p][3], bWl + off);
            }
            #pragma unroll
            for (int a = 0; a < 4; ++a)
                #pragma unroll
                for (int p = 0; p < 2; ++p)
                    #pragma unroll
                    for (int hq = 0; hq < 2; ++hq) {
                        int nb = p * 2 + hq;
                        MMA_F16(acc[a][nb], af[a], bh[p][hq*2], bh[p][hq*2+1]);
                        MMA_F16(acc[a][nb], af[a], bl[p][hq*2], bl[p][hq*2+1]);
                    }
        }
        // no tail barrier: next iteration's top sync covers stage reuse
    }

    // Epilogue: f32 out, or bf16 hi/lo split (exact split of computed value)
    #pragma unroll
    for (int a = 0; a < 4; ++a) {
        int r_lo = m0 + warp_m * 64 + a * 16 + (lane >> 2);
        #pragma unroll
        for (int nb = 0; nb < 4; ++nb) {
            int c = n0 + warp_n * 32 + nb * 8 + (lane & 3) * 2;
            float b0 = bias[c], b1 = bias[c + 1];
            float y00 = acc[a][nb][0] + b0, y01 = acc[a][nb][1] + b1;
            float y10 = acc[a][nb][2] + b0, y11 = acc[a][nb][3] + b1;
            if (Ch) {
                y00 *= oscale; y01 *= oscale; y10 *= oscale; y11 *= oscale;
                uint32_t h, l;
                split2(y00, y01, h, l);
                *reinterpret_cast<uint32_t*>(Ch + (size_t)r_lo * N + c) = h;
                *reinterpret_cast<uint32_t*>(Cl + (size_t)r_lo * N + c) = l;
                split2(y10, y11, h, l);
                *reinterpret_cast<uint32_t*>(Ch + (size_t)(r_lo + 8) * N + c) = h;
                *reinterpret_cast<uint32_t*>(Cl + (size_t)(r_lo + 8) * N + c) = l;
            } else {
                float2 v0 = { y00, y01 }, v1 = { y10, y11 };
                *reinterpret_cast<float2*>(C + (size_t)r_lo * N + c) = v0;
                *reinterpret_cast<float2*>(C + (size_t)(r_lo + 8) * N + c) = v1;
            }
        }
    }
}

// ===========================================================================
// Tensor-core flash attention (split-bf16 3-pass, no mask) — mainloop
// unchanged from R12/R13 WIN. Epilogue now emits single fp16 (for 2-pass
// O-projection).
// ===========================================================================
#define FA_BQ   128
#define FA_BKV  64
#define FA_STR  136
#define FA_KT   (FA_BKV * FA_STR)
#define FA_STAGE (4 * FA_KT)
#define FA_QT   (FA_BQ * FA_STR)
#define FA_SMEM_B ((2 * FA_STAGE + 2 * FA_QT) * 2)   // 208896 bytes

__global__ __launch_bounds__(256, 1) void flash_mma(
    const __nv_bfloat16* __restrict__ qh, const __nv_bfloat16* __restrict__ ql,
    const __nv_bfloat16* __restrict__ kh, const __nv_bfloat16* __restrict__ kl,
    const __nv_bfloat16* __restrict__ vh, const __nv_bfloat16* __restrict__ vl,
    __half* __restrict__ o16)
{
    extern __shared__ __nv_bfloat16 fsm[];
    const int tid  = threadIdx.x;
    const int lane = tid & 31;
    const int wid  = tid >> 5;
    const int q0   = blockIdx.x * FA_BQ;
    const int bh_i = blockIdx.y;
    const int b = bh_i >> 4, h = bh_i & 15;
    const size_t rowbase = (size_t)b * SEQ;
    const size_t cbase   = (size_t)h * HD;

    const uint32_t smb  = smem_u32(fsm);
    const uint32_t Qh_b = smb + 2 * FA_STAGE * 2;
    const uint32_t Ql_b = Qh_b + FA_QT * 2;

    // Q tile loads: 128 rows x 16 granules x {hi,lo}; 2048 granules/tensor.
    #pragma unroll
    for (int i = 0; i < 8; ++i) {
        int g = tid + i * 256;
        int r = g >> 4, c = g & 15;
        size_t src = (rowbase + q0 + r) * HID + cbase + c * 8;
        uint32_t doff = (uint32_t)(r * FA_STR + c * 8) * 2;
        CP_ASYNC16(Qh_b + doff, qh + src);
        CP_ASYNC16(Ql_b + doff, ql + src);
    }
    CP_COMMIT();

    auto load_kv = [&](int ck, int s) {
        uint32_t stage_b = smb + (uint32_t)s * FA_STAGE * 2;
        const __nv_bfloat16* gsrc[4] = { kh, kl, vh, vl };
        #pragma unroll
        for (int i = 0; i < 4; ++i) {
            int g = tid + i * 256;
            int r = g >> 4, c = g & 15;
            size_t src = (rowbase + ck * FA_BKV + r) * HID + cbase + c * 8;
            uint32_t doff = (uint32_t)(r * FA_STR + c * 8) * 2;
            #pragma unroll
            for (int t = 0; t < 4; ++t)
                CP_ASYNC16(stage_b + (uint32_t)t * FA_KT * 2 + doff, gsrc[t] + src);
        }
    };
    load_kv(0, 0); CP_COMMIT();
    load_kv(1, 1); CP_COMMIT();

    CP_WAIT2();
    __syncthreads();
    uint32_t qfh[8][4];
    const int arow = wid * 16 + (lane & 15);
    const int aksel = (lane >> 4) << 3;
    #pragma unroll
    for (int ks = 0; ks < 8; ++ks) {
        uint32_t off = (uint32_t)(arow * FA_STR + ks * 16 + aksel) * 2;
        LDMATRIX_X4(qfh[ks][0], qfh[ks][1], qfh[ks][2], qfh[ks][3], Qh_b + off);
    }

    float m0v = -1e30f, m1v = -1e30f, l0 = 0.0f, l1 = 0.0f;
    float acc_o[16][4];
    #pragma unroll
    for (int nf = 0; nf < 16; ++nf)
        #pragma unroll
        for (int c = 0; c < 4; ++c) acc_o[nf][c] = 0.0f;

    const int nrow  = ((lane >> 4) << 3) + (lane & 7);
    const int kksel = ((lane >> 3) & 1) * 8;
    const int vrow  = lane & 15;
    const int vcol8 = (lane >> 4) << 3;

    for (int ck = 0; ck < SEQ / FA_BKV; ++ck) {
        const int s = ck & 1;
        CP_WAIT1();
        __syncthreads();

        uint32_t stage_b = smb + (uint32_t)s * FA_STAGE * 2;
        uint32_t Kh_b = stage_b;
        uint32_t Kl_b = stage_b + FA_KT * 2;
        uint32_t Vh_b = stage_b + 2 * FA_KT * 2;
        uint32_t Vl_b = stage_b + 3 * FA_KT * 2;

        float accs[8][4];
        #pragma unroll
        for (int j = 0; j < 8; ++j)
            #pragma unroll
            for (int c = 0; c < 4; ++c) accs[j][c] = 0.0f;

        #pragma unroll
        for (int ks = 0; ks < 8; ++ks) {
            uint32_t qlo[4];
            {
                uint32_t off = (uint32_t)(arow * FA_STR + ks * 16 + aksel) * 2;
                LDMATRIX_X4(qlo[0], qlo[1], qlo[2], qlo[3], Ql_b + off);
            }
            #pragma unroll
            for (int g4 = 0; g4 < 4; ++g4) {
                uint32_t off = (uint32_t)((g4 * 16 + nrow) * FA_STR + ks * 16 + kksel) * 2;
                uint32_t kbh[4], kbl[4];
                LDMATRIX_X4(kbh[0], kbh[1], kbh[2], kbh[3], Kh_b + off);
                LDMATRIX_X4(kbl[0], kbl[1], kbl[2], kbl[3], Kl_b + off);
                MMA_BF16(accs[g4*2],   qfh[ks], kbh[0], kbh[1]);
                MMA_BF16(accs[g4*2],   qfh[ks], kbl[0], kbl[1]);
                MMA_BF16(accs[g4*2],   qlo,     kbh[0], kbh[1]);
                MMA_BF16(accs[g4*2+1], qfh[ks], kbh[2], kbh[3]);
                MMA_BF16(accs[g4*2+1], qfh[ks], kbl[2], kbl[3]);
                MMA_BF16(accs[g4*2+1], qlo,     kbh[2], kbh[3]);
            }
        }

        // online softmax (warp-local)
        float mx0 = -1e30f, mx1 = -1e30f;
        #pragma unroll
        for (int j = 0; j < 8; ++j) {
            mx0 = fmaxf(mx0, fmaxf(accs[j][0], accs[j][1]));
            mx1 = fmaxf(mx1, fmaxf(accs[j][2], accs[j][3]));
        }
        mx0 = fmaxf(mx0, __shfl_xor_sync(0xffffffffu, mx0, 1));
        mx0 = fmaxf(mx0, __shfl_xor_sync(0xffffffffu, mx0, 2));
        mx1 = fmaxf(mx1, __shfl_xor_sync(0xffffffffu, mx1, 1));
        mx1 = fmaxf(mx1, __shfl_xor_sync(0xffffffffu, mx1, 2));

        float mn0 = fmaxf(m0v, mx0), mn1 = fmaxf(m1v, mx1);
        float corr0 = __expf(m0v - mn0), corr1 = __expf(m1v - mn1);
        m0v = mn0; m1v = mn1;

        float sum0 = 0.0f, sum1 = 0.0f;
        #pragma unroll
        for (int j = 0; j < 8; ++j) {
            accs[j][0] = __expf(accs[j][0] - mn0);
            accs[j][1] = __expf(accs[j][1] - mn0);
            accs[j][2] = __expf(accs[j][2] - mn1);
            accs[j][3] = __expf(accs[j][3] - mn1);
            sum0 += accs[j][0] + accs[j][1];
            sum1 += accs[j][2] + accs[j][3];
        }
        sum0 += __shfl_xor_sync(0xffffffffu, sum0, 1);
        sum0 += __shfl_xor_sync(0xffffffffu, sum0, 2);
        sum1 += __shfl_xor_sync(0xffffffffu, sum1, 1);
        sum1 += __shfl_xor_sync(0xffffffffu, sum1, 2);
        l0 = l0 * corr0 + sum0;
        l1 = l1 * corr1 + sum1;

        #pragma unroll
        for (int nf = 0; nf < 16; ++nf) {
            acc_o[nf][0] *= corr0; acc_o[nf][1] *= corr0;
            acc_o[nf][2] *= corr1; acc_o[nf][3] *= corr1;
        }

        // P fragments (bf16 hi/lo from registers)
        uint32_t pfh[4][4], pfl[4][4];
        #pragma unroll
        for (int t = 0; t < 4; ++t) {
            int j0 = 2 * t, j1 = 2 * t + 1;
            split2(accs[j0][0], accs[j0][1], pfh[t][0], pfl[t][0]);
            split2(accs[j0][2], accs[j0][3], pfh[t][1], pfl[t][1]);
            split2(accs[j1][0], accs[j1][1], pfh[t][2], pfl[t][2]);
            split2(accs[j1][2], accs[j1][3], pfh[t][3], pfl[t][3]);
        }

        // O += P V (3-pass split); V via ldmatrix.trans
        #pragma unroll
        for (int t = 0; t < 4; ++t) {
            #pragma unroll
            for (int g8 = 0; g8 < 8; ++g8) {
                uint32_t off = (uint32_t)((t * 16 + vrow) * FA_STR + g8 * 16 + vcol8) * 2;
                uint32_t vbh[4], vbl[4];
                LDMATRIX_X4_T(vbh[0], vbh[1], vbh[2], vbh[3], Vh_b + off);
                LDMATRIX_X4_T(vbl[0], vbl[1], vbl[2], vbl[3], Vl_b + off);
                int nf0 = g8 * 2, nf1 = nf0 + 1;
                MMA_BF16(acc_o[nf0], pfh[t], vbh[0], vbh[1]);
                MMA_BF16(acc_o[nf0], pfh[t], vbl[0], vbl[1]);
                MMA_BF16(acc_o[nf0], pfl[t], vbh[0], vbh[1]);
                MMA_BF16(acc_o[nf1], pfh[t], vbh[2], vbh[3]);
                MMA_BF16(acc_o[nf1], pfh[t], vbl[2], vbl[3]);
                MMA_BF16(acc_o[nf1], pfl[t], vbh[2], vbh[3]);
            }
        }

        __syncthreads();
        if (ck + 2 < SEQ / FA_BKV) load_kv(ck + 2, s);
        CP_COMMIT();
    }

    // epilogue: normalize, single fp16 output
    float inv0 = 1.0f / l0, inv1 = 1.0f / l1;
    int r0 = q0 + wid * 16 + (lane >> 2);
    int r1 = r0 + 8;
    #pragma unroll
    for (int g8 = 0; g8 < 8; ++g8) {
        #pragma unroll
        for (int half = 0; half < 2; ++half) {
            int nf = g8 * 2 + half;
            int c = g8 * 16 + half * 8 + (lane & 3) * 2;
            size_t o0 = (rowbase + r0) * HID + cbase + c;
            size_t o1 = (rowbase + r1) * HID + cbase + c;
            __half2 h0 = __floats2half2_rn(acc_o[nf][0] * inv0, acc_o[nf][1] * inv0);
            __half2 h1 = __floats2half2_rn(acc_o[nf][2] * inv1, acc_o[nf][3] * inv1);
            *reinterpret_cast<uint32_t*>(o16 + o0) = *reinterpret_cast<uint32_t*>(&h0);
            *reinterpret_cast<uint32_t*>(o16 + o1) = *reinterpret_cast<uint32_t*>(&h1);
        }
    }
}

// ---------------------------------------------------------------------------
// Launch
// ---------------------------------------------------------------------------
extern "C" void kernel_launch(void* const* d_in, const int* in_sizes, int n_in,
                              void* d_out, int out_size)
{
    const float* x  = (const float*)d_in[0];
    const float* Wq = (const float*)d_in[1];
    const float* bq = (const float*)d_in[2];
    const float* Wk = (const float*)d_in[3];
    const float* bk = (const float*)d_in[4];
    const float* Wv = (const float*)d_in[5];
    const float* bv = (const float*)d_in[6];
    const float* Wo = (const float*)d_in[7];
    const float* bo = (const float*)d_in[8];
    float* out = (float*)d_out;

    __half *x16, *a16, *Whb, *Wlb;
    __nv_bfloat16 *qh, *ql, *kh, *kl, *vh, *vl;
    cudaGetSymbolAddress((void**)&x16, g_x16);
    cudaGetSymbolAddress((void**)&a16, g_a16);
    cudaGetSymbolAddress((void**)&Whb, g_Wh);
    cudaGetSymbolAddress((void**)&Wlb, g_Wl);
    cudaGetSymbolAddress((void**)&qh, g_qh);
    cudaGetSymbolAddress((void**)&ql, g_ql);
    cudaGetSymbolAddress((void**)&kh, g_kh);
    cudaGetSymbolAddress((void**)&kl, g_kl);
    cudaGetSymbolAddress((void**)&vh, g_vh);
    cudaGetSymbolAddress((void**)&vl, g_vl);

    cudaFuncSetAttribute(gemm_mma,
                         cudaFuncAttributeMaxDynamicSharedMemorySize, GEMM_SMEM_B);
    cudaFuncSetAttribute(flash_mma,
                         cudaFuncAttributeMaxDynamicSharedMemorySize, FA_SMEM_B);

    // Conversions: x -> fp16; W's -> fp16 hi/lo
    const int n4x = (int)(MSZ / 4), n4w = (int)(WSZ / 4);
    cvt_f16_kernel<<<(n4x + 255) / 256, 256>>>(x, x16, n4x);
    const float* Ws[4] = { Wq, Wk, Wv, Wo };
    for (int i = 0; i < 4; ++i)
        split_f16hl_kernel<<<(n4w + 255) / 256, 256>>>(
            Ws[i], Whb + (size_t)i * WSZ, Wlb + (size_t)i * WSZ, n4w);

    const float scale = 1.0f / sqrtf((float)HD);

    // Fused Q/K/V projections: one launch, which = blockIdx.x>>4
    dim3 qkv_grid(3 * (HID / GN), MROWS / GM);   // (48, 32)
    gemm_mma<<<qkv_grid, 256, GEMM_SMEM_B>>>(
        x16, Whb, Wlb, bq, bk, bv,
        nullptr, qh, ql, kh, kl, vh, vl,
        scale, MROWS, HID, HID);

    dim3 fgrid(SEQ / FA_BQ, BATCH * HEADS);  // (16, 32)
    flash_mma<<<fgrid, 256, FA_SMEM_B>>>(qh, ql, kh, kl, vh, vl, a16);

    // Output projection -> f32 result (which=0 only)
    dim3 ogrid(HID / GN, MROWS / GM);   // (16, 32)
    gemm_mma<<<ogrid, 256, GEMM_SMEM_B>>>(
        a16, Whb + 3 * WSZ, Wlb + 3 * WSZ, bo, nullptr, nullptr,
        out, nullptr, nullptr, nullptr, nullptr, nullptr, nullptr,
        1.0f, MROWS, HID, HID);
}

// round 16
// speedup vs baseline: 3.3271x; 1.0583x over previous
#include <cuda_runtime.h>
#include <cuda_bf16.h>
#include <cuda_fp16.h>
#include <math.h>
#include <stdint.h>

// Problem constants
#define BATCH   2
#define SEQ     2048
#define HID     2048
#define HEADS   16
#define HD      128
#define MROWS   (BATCH * SEQ)          // 4096
#define MSZ     ((size_t)MROWS * HID)  // 8M elements
#define WSZ     ((size_t)HID * HID)    // 4M elements

// fp16 GEMM operands (A single, W hi/lo)
__device__ __half g_x16[MSZ];
__device__ __half g_a16[MSZ];
__device__ __half g_Wh[4][WSZ], g_Wl[4][WSZ];
// bf16 hi/lo split Q/K/V for flash (3-pass path, unchanged)
__device__ __nv_bfloat16 g_qh[MSZ], g_ql[MSZ];
__device__ __nv_bfloat16 g_kh[MSZ], g_kl[MSZ];
__device__ __nv_bfloat16 g_vh[MSZ], g_vl[MSZ];

// ===========================================================================
// Helpers
// ===========================================================================
__device__ __forceinline__ uint32_t smem_u32(const void* p) {
    uint32_t a;
    asm("{ .reg .u64 t; cvta.to.shared.u64 t, %1; cvt.u32.u64 %0, t; }"
        : "=r"(a) : "l"(p));
    return a;
}

#define CP_ASYNC16(dst, src) \
    asm volatile("cp.async.cg.shared.global [%0], [%1], 16;" \
        :: "r"(dst), "l"(src))
#define CP_COMMIT() asm volatile("cp.async.commit_group;" ::: "memory")
#define CP_WAIT1()  asm volatile("cp.async.wait_group 1;" ::: "memory")
#define CP_WAIT2()  asm volatile("cp.async.wait_group 2;" ::: "memory")

#define LDMATRIX_X4(r0, r1, r2, r3, addr) \
    asm volatile("ldmatrix.sync.aligned.m8n8.x4.shared.b16 {%0,%1,%2,%3}, [%4];" \
        : "=r"(r0), "=r"(r1), "=r"(r2), "=r"(r3) : "r"(addr))

#define LDMATRIX_X4_T(r0, r1, r2, r3, addr) \
    asm volatile("ldmatrix.sync.aligned.m8n8.x4.trans.shared.b16 {%0,%1,%2,%3}, [%4];" \
        : "=r"(r0), "=r"(r1), "=r"(r2), "=r"(r3) : "r"(addr))

#define MMA_BF16(c, a, b0, b1) \
    asm volatile("mma.sync.aligned.m16n8k16.row.col.f32.bf16.bf16.f32 " \
        "{%0,%1,%2,%3}, {%4,%5,%6,%7}, {%8,%9}, {%0,%1,%2,%3};" \
        : "+f"((c)[0]), "+f"((c)[1]), "+f"((c)[2]), "+f"((c)[3]) \
        : "r"((a)[0]), "r"((a)[1]), "r"((a)[2]), "r"((a)[3]), "r"(b0), "r"(b1))

#define MMA_F16(c, a, b0, b1) \
    asm volatile("mma.sync.aligned.m16n8k16.row.col.f32.f16.f16.f32 " \
        "{%0,%1,%2,%3}, {%4,%5,%6,%7}, {%8,%9}, {%0,%1,%2,%3};" \
        : "+f"((c)[0]), "+f"((c)[1]), "+f"((c)[2]), "+f"((c)[3]) \
        : "r"((a)[0]), "r"((a)[1]), "r"((a)[2]), "r"((a)[3]), "r"(b0), "r"(b1))

// split a pair of floats into packed bf16x2 hi and lo words
__device__ __forceinline__ void split2(float a, float b, uint32_t& hi, uint32_t& lo) {
    __nv_bfloat16 ha = __float2bfloat16_rn(a);
    __nv_bfloat16 hb = __float2bfloat16_rn(b);
    hi = (uint32_t)__bfloat16_as_ushort(ha) | ((uint32_t)__bfloat16_as_ushort(hb) << 16);
    __nv_bfloat162 l = __floats2bfloat162_rn(a - __bfloat162float(ha),
                                             b - __bfloat162float(hb));
    lo = *reinterpret_cast<uint32_t*>(&l);
}

// split a pair of floats into packed fp16x2 hi and lo words
__device__ __forceinline__ void split2h(float a, float b, uint32_t& hi, uint32_t& lo) {
    __half ha = __float2half_rn(a);
    __half hb = __float2half_rn(b);
    hi = (uint32_t)__half_as_ushort(ha) | ((uint32_t)__half_as_ushort(hb) << 16);
    __half2 l = __floats2half2_rn(a - __half2float(ha), b - __half2float(hb));
    lo = *reinterpret_cast<uint32_t*>(&l);
}

// ===========================================================================
// Conversion kernels
// ===========================================================================
// f32 -> fp16 hi/lo split (weights)
__global__ __launch_bounds__(256) void split_f16hl_kernel(
    const float* __restrict__ src, __half* __restrict__ hi,
    __half* __restrict__ lo, int n4)
{
    int i = blockIdx.x * blockDim.x + threadIdx.x;
    if (i >= n4) return;
    float4 v = reinterpret_cast<const float4*>(src)[i];
    uint32_t h0, l0, h1, l1;
    split2h(v.x, v.y, h0, l0);
    split2h(v.z, v.w, h1, l1);
    uint2 hv = { h0, h1 }, lv = { l0, l1 };
    reinterpret_cast<uint2*>(hi)[i] = hv;
    reinterpret_cast<uint2*>(lo)[i] = lv;
}

// f32 -> fp16 (activations; single word)
__global__ __launch_bounds__(256) void cvt_f16_kernel(
    const float* __restrict__ src, __half* __restrict__ dst, int n4)
{
    int i = blockIdx.x * blockDim.x + threadIdx.x;
    if (i >= n4) return;
    float4 v = reinterpret_cast<const float4*>(src)[i];
    __half2 a = __floats2half2_rn(v.x, v.y);
    __half2 b = __floats2half2_rn(v.z, v.w);
    uint2 o = { *reinterpret_cast<uint32_t*>(&a), *reinterpret_cast<uint32_t*>(&b) };
    reinterpret_cast<uint2*>(dst)[i] = o;
}

// ===========================================================================
// fp16 2-pass tensor-core GEMM, 2-stage cp.async pipeline, 2 CTAs/SM:
//   C = A16 @ Wh^T + A16 @ Wl^T + bias ; blockIdx.x>>4 selects W/bias/output.
// 3 smem tiles per stage (A, Wh, Wl). smem 110,592 B -> 2 CTAs resident.
// ===========================================================================
#define GM 128
#define GN 128
#define KC 64
#define NCHUNK (HID / KC)     // 32
#define GSTR 72
#define TELEM (128 * GSTR)    // 9216 elems per tile
#define STAGE_ELEM (3 * TELEM)
#define NSTAGE 2
#define GEMM_SMEM_B (NSTAGE * STAGE_ELEM * 2)   // 110592 bytes

__global__ __launch_bounds__(256, 2) void gemm_mma(
    const __half* __restrict__ A,
    const __half* __restrict__ WhB, const __half* __restrict__ WlB,
    const float* __restrict__ bias0, const float* __restrict__ bias1,
    const float* __restrict__ bias2,
    float* __restrict__ C,
    __nv_bfloat16* __restrict__ Ch0, __nv_bfloat16* __restrict__ Cl0,
    __nv_bfloat16* __restrict__ Ch1, __nv_bfloat16* __restrict__ Cl1,
    __nv_bfloat16* __restrict__ Ch2, __nv_bfloat16* __restrict__ Cl2,
    float oscale0, int M, int N, int K)
{
    extern __shared__ __half sm[];
    const int tid  = threadIdx.x;
    const int lane = tid & 31;
    const int wid  = tid >> 5;
    const int warp_m = wid >> 2;
    const int warp_n = wid & 3;
    const int which = blockIdx.x >> 4;               // 0..2 matrix selector
    const int n0 = (blockIdx.x & 15) * GN;
    const int m0 = blockIdx.y * GM;

    const __half* Wh = WhB + (size_t)which * WSZ;
    const __half* Wl = WlB + (size_t)which * WSZ;
    const float* bias = (which == 0) ? bias0 : (which == 1) ? bias1 : bias2;
    __nv_bfloat16* Ch = (which == 0) ? Ch0 : (which == 1) ? Ch1 : Ch2;
    __nv_bfloat16* Cl = (which == 0) ? Cl0 : (which == 1) ? Cl1 : Cl2;
    const float oscale = (which == 0) ? oscale0 : 1.0f;

    const uint32_t smb = smem_u32(sm);

    float acc[4][4][4];
    #pragma unroll
    for (int a = 0; a < 4; ++a)
        #pragma unroll
        for (int b = 0; b < 4; ++b)
            #pragma unroll
            for (int c = 0; c < 4; ++c) acc[a][b][c] = 0.0f;

    int lrow[4], lcol[4];
    #pragma unroll
    for (int i = 0; i < 4; ++i) {
        int linear = tid + i * 256;       // 0..1023 granules per tile
        lrow[i] = linear >> 3;
        lcol[i] = (linear & 7) * 8;
    }

    auto load_chunk = [&](int ck, int s) {
        const int k0 = ck * KC;
        uint32_t stage_b = smb + (uint32_t)s * STAGE_ELEM * 2;
        const __half* gsrc[3] = {
            A + (size_t)m0 * K + k0,
            Wh + (size_t)n0 * K + k0, Wl + (size_t)n0 * K + k0 };
        #pragma unroll
        for (int t = 0; t < 3; ++t) {
            uint32_t tb = stage_b + (uint32_t)t * TELEM * 2;
            #pragma unroll
            for (int i = 0; i < 4; ++i) {
                uint32_t dst = tb + (uint32_t)(lrow[i] * GSTR + lcol[i]) * 2;
                const __half* src = gsrc[t] + (size_t)lrow[i] * K + lcol[i];
                CP_ASYNC16(dst, src);
            }
        }
    };

    load_chunk(0, 0); CP_COMMIT();
    load_chunk(1, 1); CP_COMMIT();

    const int arow  = warp_m * 64 + (lane & 15);
    const int aksel = (lane >> 4) << 3;
    const int brow  = warp_n * 32 + ((lane >> 4) << 3) + (lane & 7);
    const int bksel = ((lane >> 3) & 1) * 8;

    for (int ck = 0; ck < NCHUNK; ++ck) {
        const int s = ck & 1;
        CP_WAIT1();
        __syncthreads();

        uint32_t stage_b = smb + (uint32_t)s * STAGE_ELEM * 2;
        uint32_t bA  = stage_b;
        uint32_t bWh = stage_b + TELEM * 2;
        uint32_t bWl = stage_b + 2 * TELEM * 2;

        #pragma unroll
        for (int ks = 0; ks < KC / 16; ++ks) {
            const int akoff = ks * 16 + aksel;
            const int bkoff = ks * 16 + bksel;

            uint32_t af[4][4];
            #pragma unroll
            for (int a = 0; a < 4; ++a) {
                uint32_t off = (uint32_t)((arow + a * 16) * GSTR + akoff) * 2;
                LDMATRIX_X4(af[a][0], af[a][1], af[a][2], af[a][3], bA + off);
            }
            uint32_t bh[2][4], bl[2][4];
            #pragma unroll
            for (int p = 0; p < 2; ++p) {
                uint32_t off = (uint32_t)((brow + p * 16) * GSTR + bkoff) * 2;
                LDMATRIX_X4(bh[p][0], bh[p][1], bh[p][2], bh[p][3], bWh + off);
                LDMATRIX_X4(bl[p][0], bl[p][1], bl[p][2], bl[p][3], bWl + off);
            }
            #pragma unroll
            for (int a = 0; a < 4; ++a)
                #pragma unroll
                for (int p = 0; p < 2; ++p)
                    #pragma unroll
                    for (int hq = 0; hq < 2; ++hq) {
                        int nb = p * 2 + hq;
                        MMA_F16(acc[a][nb], af[a], bh[p][hq*2], bh[p][hq*2+1]);
                        MMA_F16(acc[a][nb], af[a], bl[p][hq*2], bl[p][hq*2+1]);
                    }
        }
        __syncthreads();
        if (ck + 2 < NCHUNK) load_chunk(ck + 2, s);
        CP_COMMIT();
    }

    // Epilogue: f32 out, or bf16 hi/lo split (exact split of computed value)
    #pragma unroll
    for (int a = 0; a < 4; ++a) {
        int r_lo = m0 + warp_m * 64 + a * 16 + (lane >> 2);
        #pragma unroll
        for (int nb = 0; nb < 4; ++nb) {
            int c = n0 + warp_n * 32 + nb * 8 + (lane & 3) * 2;
            float b0 = bias[c], b1 = bias[c + 1];
            float y00 = acc[a][nb][0] + b0, y01 = acc[a][nb][1] + b1;
            float y10 = acc[a][nb][2] + b0, y11 = acc[a][nb][3] + b1;
            if (Ch) {
                y00 *= oscale; y01 *= oscale; y10 *= oscale; y11 *= oscale;
                uint32_t h, l;
                split2(y00, y01, h, l);
                *reinterpret_cast<uint32_t*>(Ch + (size_t)r_lo * N + c) = h;
                *reinterpret_cast<uint32_t*>(Cl + (size_t)r_lo * N + c) = l;
                split2(y10, y11, h, l);
                *reinterpret_cast<uint32_t*>(Ch + (size_t)(r_lo + 8) * N + c) = h;
                *reinterpret_cast<uint32_t*>(Cl + (size_t)(r_lo + 8) * N + c) = l;
            } else {
                float2 v0 = { y00, y01 }, v1 = { y10, y11 };
                *reinterpret_cast<float2*>(C + (size_t)r_lo * N + c) = v0;
                *reinterpret_cast<float2*>(C + (size_t)(r_lo + 8) * N + c) = v1;
            }
        }
    }
}

// ===========================================================================
// Tensor-core flash attention (split-bf16 3-pass, no mask) — unchanged
// mainloop; epilogue emits single fp16 (for 2-pass O-projection).
// ===========================================================================
#define FA_BQ   128
#define FA_BKV  64
#define FA_STR  136
#define FA_KT   (FA_BKV * FA_STR)
#define FA_STAGE (4 * FA_KT)
#define FA_QT   (FA_BQ * FA_STR)
#define FA_SMEM_B ((2 * FA_STAGE + 2 * FA_QT) * 2)   // 208896 bytes

__global__ __launch_bounds__(256, 1) void flash_mma(
    const __nv_bfloat16* __restrict__ qh, const __nv_bfloat16* __restrict__ ql,
    const __nv_bfloat16* __restrict__ kh, const __nv_bfloat16* __restrict__ kl,
    const __nv_bfloat16* __restrict__ vh, const __nv_bfloat16* __restrict__ vl,
    __half* __restrict__ o16)
{
    extern __shared__ __nv_bfloat16 fsm[];
    const int tid  = threadIdx.x;
    const int lane = tid & 31;
    const int wid  = tid >> 5;
    const int q0   = blockIdx.x * FA_BQ;
    const int bh_i = blockIdx.y;
    const int b = bh_i >> 4, h = bh_i & 15;
    const size_t rowbase = (size_t)b * SEQ;
    const size_t cbase   = (size_t)h * HD;

    const uint32_t smb  = smem_u32(fsm);
    const uint32_t Qh_b = smb + 2 * FA_STAGE * 2;
    const uint32_t Ql_b = Qh_b + FA_QT * 2;

    // Q tile loads: 128 rows x 16 granules x {hi,lo}; 2048 granules/tensor.
    #pragma unroll
    for (int i = 0; i < 8; ++i) {
        int g = tid + i * 256;
        int r = g >> 4, c = g & 15;
        size_t src = (rowbase + q0 + r) * HID + cbase + c * 8;
        uint32_t doff = (uint32_t)(r * FA_STR + c * 8) * 2;
        CP_ASYNC16(Qh_b + doff, qh + src);
        CP_ASYNC16(Ql_b + doff, ql + src);
    }
    CP_COMMIT();

    auto load_kv = [&](int ck, int s) {
        uint32_t stage_b = smb + (uint32_t)s * FA_STAGE * 2;
        const __nv_bfloat16* gsrc[4] = { kh, kl, vh, vl };
        #pragma unroll
        for (int i = 0; i < 4; ++i) {
            int g = tid + i * 256;
            int r = g >> 4, c = g & 15;
            size_t src = (rowbase + ck * FA_BKV + r) * HID + cbase + c * 8;
            uint32_t doff = (uint32_t)(r * FA_STR + c * 8) * 2;
            #pragma unroll
            for (int t = 0; t < 4; ++t)
                CP_ASYNC16(stage_b + (uint32_t)t * FA_KT * 2 + doff, gsrc[t] + src);
        }
    };
    load_kv(0, 0); CP_COMMIT();
    load_kv(1, 1); CP_COMMIT();

    CP_WAIT2();
    __syncthreads();
    uint32_t qfh[8][4];
    const int arow = wid * 16 + (lane & 15);
    const int aksel = (lane >> 4) << 3;
    #pragma unroll
    for (int ks = 0; ks < 8; ++ks) {
        uint32_t off = (uint32_t)(arow * FA_STR + ks * 16 + aksel) * 2;
        LDMATRIX_X4(qfh[ks][0], qfh[ks][1], qfh[ks][2], qfh[ks][3], Qh_b + off);
    }

    float m0v = -1e30f, m1v = -1e30f, l0 = 0.0f, l1 = 0.0f;
    float acc_o[16][4];
    #pragma unroll
    for (int nf = 0; nf < 16; ++nf)
        #pragma unroll
        for (int c = 0; c < 4; ++c) acc_o[nf][c] = 0.0f;

    const int nrow  = ((lane >> 4) << 3) + (lane & 7);
    const int kksel = ((lane >> 3) & 1) * 8;
    const int vrow  = lane & 15;
    const int vcol8 = (lane >> 4) << 3;

    for (int ck = 0; ck < SEQ / FA_BKV; ++ck) {
        const int s = ck & 1;
        CP_WAIT1();
        __syncthreads();

        uint32_t stage_b = smb + (uint32_t)s * FA_STAGE * 2;
        uint32_t Kh_b = stage_b;
        uint32_t Kl_b = stage_b + FA_KT * 2;
        uint32_t Vh_b = stage_b + 2 * FA_KT * 2;
        uint32_t Vl_b = stage_b + 3 * FA_KT * 2;

        float accs[8][4];
        #pragma unroll
        for (int j = 0; j < 8; ++j)
            #pragma unroll
            for (int c = 0; c < 4; ++c) accs[j][c] = 0.0f;

        #pragma unroll
        for (int ks = 0; ks < 8; ++ks) {
            uint32_t qlo[4];
            {
                uint32_t off = (uint32_t)(arow * FA_STR + ks * 16 + aksel) * 2;
                LDMATRIX_X4(qlo[0], qlo[1], qlo[2], qlo[3], Ql_b + off);
            }
            #pragma unroll
            for (int g4 = 0; g4 < 4; ++g4) {
                uint32_t off = (uint32_t)((g4 * 16 + nrow) * FA_STR + ks * 16 + kksel) * 2;
                uint32_t kbh[4], kbl[4];
                LDMATRIX_X4(kbh[0], kbh[1], kbh[2], kbh[3], Kh_b + off);
                LDMATRIX_X4(kbl[0], kbl[1], kbl[2], kbl[3], Kl_b + off);
                MMA_BF16(accs[g4*2],   qfh[ks], kbh[0], kbh[1]);
                MMA_BF16(accs[g4*2],   qfh[ks], kbl[0], kbl[1]);
                MMA_BF16(accs[g4*2],   qlo,     kbh[0], kbh[1]);
                MMA_BF16(accs[g4*2+1], qfh[ks], kbh[2], kbh[3]);
                MMA_BF16(accs[g4*2+1], qfh[ks], kbl[2], kbl[3]);
                MMA_BF16(accs[g4*2+1], qlo,     kbh[2], kbh[3]);
            }
        }

        // online softmax (warp-local)
        float mx0 = -1e30f, mx1 = -1e30f;
        #pragma unroll
        for (int j = 0; j < 8; ++j) {
            mx0 = fmaxf(mx0, fmaxf(accs[j][0], accs[j][1]));
            mx1 = fmaxf(mx1, fmaxf(accs[j][2], accs[j][3]));
        }
        mx0 = fmaxf(mx0, __shfl_xor_sync(0xffffffffu, mx0, 1));
        mx0 = fmaxf(mx0, __shfl_xor_sync(0xffffffffu, mx0, 2));
        mx1 = fmaxf(mx1, __shfl_xor_sync(0xffffffffu, mx1, 1));
        mx1 = fmaxf(mx1, __shfl_xor_sync(0xffffffffu, mx1, 2));

        float mn0 = fmaxf(m0v, mx0), mn1 = fmaxf(m1v, mx1);
        float corr0 = __expf(m0v - mn0), corr1 = __expf(m1v - mn1);
        m0v = mn0; m1v = mn1;

        float sum0 = 0.0f, sum1 = 0.0f;
        #pragma unroll
        for (int j = 0; j < 8; ++j) {
            accs[j][0] = __expf(accs[j][0] - mn0);
            accs[j][1] = __expf(accs[j][1] - mn0);
            accs[j][2] = __expf(accs[j][2] - mn1);
            accs[j][3] = __expf(accs[j][3] - mn1);
            sum0 += accs[j][0] + accs[j][1];
            sum1 += accs[j][2] + accs[j][3];
        }
        sum0 += __shfl_xor_sync(0xffffffffu, sum0, 1);
        sum0 += __shfl_xor_sync(0xffffffffu, sum0, 2);
        sum1 += __shfl_xor_sync(0xffffffffu, sum1, 1);
        sum1 += __shfl_xor_sync(0xffffffffu, sum1, 2);
        l0 = l0 * corr0 + sum0;
        l1 = l1 * corr1 + sum1;

        #pragma unroll
        for (int nf = 0; nf < 16; ++nf) {
            acc_o[nf][0] *= corr0; acc_o[nf][1] *= corr0;
            acc_o[nf][2] *= corr1; acc_o[nf][3] *= corr1;
        }

        // P fragments (bf16 hi/lo from registers)
        uint32_t pfh[4][4], pfl[4][4];
        #pragma unroll
        for (int t = 0; t < 4; ++t) {
            int j0 = 2 * t, j1 = 2 * t + 1;
            split2(accs[j0][0], accs[j0][1], pfh[t][0], pfl[t][0]);
            split2(accs[j0][2], accs[j0][3], pfh[t][1], pfl[t][1]);
            split2(accs[j1][0], accs[j1][1], pfh[t][2], pfl[t][2]);
            split2(accs[j1][2], accs[j1][3], pfh[t][3], pfl[t][3]);
        }

        // O += P V (3-pass split); V via ldmatrix.trans
        #pragma unroll
        for (int t = 0; t < 4; ++t) {
            #pragma unroll
            for (int g8 = 0; g8 < 8; ++g8) {
                uint32_t off = (uint32_t)((t * 16 + vrow) * FA_STR + g8 * 16 + vcol8) * 2;
                uint32_t vbh[4], vbl[4];
                LDMATRIX_X4_T(vbh[0], vbh[1], vbh[2], vbh[3], Vh_b + off);
                LDMATRIX_X4_T(vbl[0], vbl[1], vbl[2], vbl[3], Vl_b + off);
                int nf0 = g8 * 2, nf1 = nf0 + 1;
                MMA_BF16(acc_o[nf0], pfh[t], vbh[0], vbh[1]);
                MMA_BF16(acc_o[nf0], pfh[t], vbl[0], vbl[1]);
                MMA_BF16(acc_o[nf0], pfl[t], vbh[0], vbh[1]);
                MMA_BF16(acc_o[nf1], pfh[t], vbh[2], vbh[3]);
                MMA_BF16(acc_o[nf1], pfh[t], vbl[2], vbl[3]);
                MMA_BF16(acc_o[nf1], pfl[t], vbh[2], vbh[3]);
            }
        }

        __syncthreads();
        if (ck + 2 < SEQ / FA_BKV) load_kv(ck + 2, s);
        CP_COMMIT();
    }

    // epilogue: normalize, single fp16 output
    float inv0 = 1.0f / l0, inv1 = 1.0f / l1;
    int r0 = q0 + wid * 16 + (lane >> 2);
    int r1 = r0 + 8;
    #pragma unroll
    for (int g8 = 0; g8 < 8; ++g8) {
        #pragma unroll
        for (int half = 0; half < 2; ++half) {
            int nf = g8 * 2 + half;
            int c = g8 * 16 + half * 8 + (lane & 3) * 2;
            size_t o0 = (rowbase + r0) * HID + cbase + c;
            size_t o1 = (rowbase + r1) * HID + cbase + c;
            __half2 h0 = __floats2half2_rn(acc_o[nf][0] * inv0, acc_o[nf][1] * inv0);
            __half2 h1 = __floats2half2_rn(acc_o[nf][2] * inv1, acc_o[nf][3] * inv1);
            *reinterpret_cast<uint32_t*>(o16 + o0) = *reinterpret_cast<uint32_t*>(&h0);
            *reinterpret_cast<uint32_t*>(o16 + o1) = *reinterpret_cast<uint32_t*>(&h1);
        }
    }
}

// ---------------------------------------------------------------------------
// Launch
// ---------------------------------------------------------------------------
extern "C" void kernel_launch(void* const* d_in, const int* in_sizes, int n_in,
                              void* d_out, int out_size)
{
    const float* x  = (const float*)d_in[0];
    const float* Wq = (const float*)d_in[1];
    const float* bq = (const float*)d_in[2];
    const float* Wk = (const float*)d_in[3];
    const float* bk = (const float*)d_in[4];
    const float* Wv = (const float*)d_in[5];
    const float* bv = (const float*)d_in[6];
    const float* Wo = (const float*)d_in[7];
    const float* bo = (const float*)d_in[8];
    float* out = (float*)d_out;

    __half *x16, *a16, *Whb, *Wlb;
    __nv_bfloat16 *qh, *ql, *kh, *kl, *vh, *vl;
    cudaGetSymbolAddress((void**)&x16, g_x16);
    cudaGetSymbolAddress((void**)&a16, g_a16);
    cudaGetSymbolAddress((void**)&Whb, g_Wh);
    cudaGetSymbolAddress((void**)&Wlb, g_Wl);
    cudaGetSymbolAddress((void**)&qh, g_qh);
    cudaGetSymbolAddress((void**)&ql, g_ql);
    cudaGetSymbolAddress((void**)&kh, g_kh);
    cudaGetSymbolAddress((void**)&kl, g_kl);
    cudaGetSymbolAddress((void**)&vh, g_vh);
    cudaGetSymbolAddress((void**)&vl, g_vl);

    cudaFuncSetAttribute(gemm_mma,
                         cudaFuncAttributeMaxDynamicSharedMemorySize, GEMM_SMEM_B);
    cudaFuncSetAttribute(flash_mma,
                         cudaFuncAttributeMaxDynamicSharedMemorySize, FA_SMEM_B);

    // Conversions: x -> fp16; W's -> fp16 hi/lo
    const int n4x = (int)(MSZ / 4), n4w = (int)(WSZ / 4);
    cvt_f16_kernel<<<(n4x + 255) / 256, 256>>>(x, x16, n4x);
    const float* Ws[4] = { Wq, Wk, Wv, Wo };
    for (int i = 0; i < 4; ++i)
        split_f16hl_kernel<<<(n4w + 255) / 256, 256>>>(
            Ws[i], Whb + (size_t)i * WSZ, Wlb + (size_t)i * WSZ, n4w);

    const float scale = 1.0f / sqrtf((float)HD);

    // Fused Q/K/V projections: one launch, which = blockIdx.x>>4
    dim3 qkv_grid(3 * (HID / GN), MROWS / GM);   // (48, 32)
    gemm_mma<<<qkv_grid, 256, GEMM_SMEM_B>>>(
        x16, Whb, Wlb, bq, bk, bv,
        nullptr, qh, ql, kh, kl, vh, vl,
        scale, MROWS, HID, HID);

    dim3 fgrid(SEQ / FA_BQ, BATCH * HEADS);  // (16, 32)
    flash_mma<<<fgrid, 256, FA_SMEM_B>>>(qh, ql, kh, kl, vh, vl, a16);

    // Output projection -> f32 result (which=0 only)
    dim3 ogrid(HID / GN, MROWS / GM);   // (16, 32)
    gemm_mma<<<ogrid, 256, GEMM_SMEM_B>>>(
        a16, Whb + 3 * WSZ, Wlb + 3 * WSZ, bo, nullptr, nullptr,
        out, nullptr, nullptr, nullptr, nullptr, nullptr, nullptr,
        1.0f, MROWS, HID, HID);
}

// round 17
// speedup vs baseline: 3.7462x; 1.1260x over previous
#include <cuda_runtime.h>
#include <cuda_bf16.h>
#include <cuda_fp16.h>
#include <math.h>
#include <stdint.h>

// Problem constants
#define BATCH   2
#define SEQ     2048
#define HID     2048
#define HEADS   16
#define HD      128
#define MROWS   (BATCH * SEQ)          // 4096
#define MSZ     ((size_t)MROWS * HID)  // 8M elements
#define WSZ     ((size_t)HID * HID)    // 4M elements

// fp16 operands
__device__ __half g_x16[MSZ];
__device__ __half g_a16[MSZ];
__device__ __half g_Wh[4][WSZ], g_Wl[4][WSZ];
__device__ __half g_q16[MSZ];
__device__ __half g_kh[MSZ], g_kl[MSZ];
__device__ __half g_vh[MSZ], g_vl[MSZ];

// ===========================================================================
// Helpers
// ===========================================================================
__device__ __forceinline__ uint32_t smem_u32(const void* p) {
    uint32_t a;
    asm("{ .reg .u64 t; cvta.to.shared.u64 t, %1; cvt.u32.u64 %0, t; }"
        : "=r"(a) : "l"(p));
    return a;
}

#define CP_ASYNC16(dst, src) \
    asm volatile("cp.async.cg.shared.global [%0], [%1], 16;" \
        :: "r"(dst), "l"(src))
#define CP_COMMIT() asm volatile("cp.async.commit_group;" ::: "memory")
#define CP_WAIT1()  asm volatile("cp.async.wait_group 1;" ::: "memory")
#define CP_WAIT2()  asm volatile("cp.async.wait_group 2;" ::: "memory")

#define LDMATRIX_X4(r0, r1, r2, r3, addr) \
    asm volatile("ldmatrix.sync.aligned.m8n8.x4.shared.b16 {%0,%1,%2,%3}, [%4];" \
        : "=r"(r0), "=r"(r1), "=r"(r2), "=r"(r3) : "r"(addr))

#define LDMATRIX_X4_T(r0, r1, r2, r3, addr) \
    asm volatile("ldmatrix.sync.aligned.m8n8.x4.trans.shared.b16 {%0,%1,%2,%3}, [%4];" \
        : "=r"(r0), "=r"(r1), "=r"(r2), "=r"(r3) : "r"(addr))

#define MMA_F16(c, a, b0, b1) \
    asm volatile("mma.sync.aligned.m16n8k16.row.col.f32.f16.f16.f32 " \
        "{%0,%1,%2,%3}, {%4,%5,%6,%7}, {%8,%9}, {%0,%1,%2,%3};" \
        : "+f"((c)[0]), "+f"((c)[1]), "+f"((c)[2]), "+f"((c)[3]) \
        : "r"((a)[0]), "r"((a)[1]), "r"((a)[2]), "r"((a)[3]), "r"(b0), "r"(b1))

// split a pair of floats into packed fp16x2 hi and lo words
__device__ __forceinline__ void split2h(float a, float b, uint32_t& hi, uint32_t& lo) {
    __half ha = __float2half_rn(a);
    __half hb = __float2half_rn(b);
    hi = (uint32_t)__half_as_ushort(ha) | ((uint32_t)__half_as_ushort(hb) << 16);
    __half2 l = __floats2half2_rn(a - __half2float(ha), b - __half2float(hb));
    lo = *reinterpret_cast<uint32_t*>(&l);
}

__device__ __forceinline__ uint32_t packh2(float a, float b) {
    __half2 h = __floats2half2_rn(a, b);
    return *reinterpret_cast<uint32_t*>(&h);
}

// ===========================================================================
// Conversion kernels
// ===========================================================================
__global__ __launch_bounds__(256) void split_f16hl_kernel(
    const float* __restrict__ src, __half* __restrict__ hi,
    __half* __restrict__ lo, int n4)
{
    int i = blockIdx.x * blockDim.x + threadIdx.x;
    if (i >= n4) return;
    float4 v = reinterpret_cast<const float4*>(src)[i];
    uint32_t h0, l0, h1, l1;
    split2h(v.x, v.y, h0, l0);
    split2h(v.z, v.w, h1, l1);
    uint2 hv = { h0, h1 }, lv = { l0, l1 };
    reinterpret_cast<uint2*>(hi)[i] = hv;
    reinterpret_cast<uint2*>(lo)[i] = lv;
}

__global__ __launch_bounds__(256) void cvt_f16_kernel(
    const float* __restrict__ src, __half* __restrict__ dst, int n4)
{
    int i = blockIdx.x * blockDim.x + threadIdx.x;
    if (i >= n4) return;
    float4 v = reinterpret_cast<const float4*>(src)[i];
    uint2 o = { packh2(v.x, v.y), packh2(v.z, v.w) };
    reinterpret_cast<uint2*>(dst)[i] = o;
}

// ===========================================================================
// fp16 2-pass tensor-core GEMM, 2-stage cp.async pipeline, 2 CTAs/SM:
//   C = A16 @ Wh^T + A16 @ Wl^T + bias ; blockIdx.x>>4 selects W/bias/output.
// Epilogue variants: f32 (C), fp16 single (Ch only), fp16 hi/lo (Ch+Cl).
// ===========================================================================
#define GM 128
#define GN 128
#define KC 64
#define NCHUNK (HID / KC)     // 32
#define GSTR 72
#define TELEM (128 * GSTR)    // 9216 elems per tile
#define STAGE_ELEM (3 * TELEM)
#define NSTAGE 2
#define GEMM_SMEM_B (NSTAGE * STAGE_ELEM * 2)   // 110592 bytes

__global__ __launch_bounds__(256, 2) void gemm_mma(
    const __half* __restrict__ A,
    const __half* __restrict__ WhB, const __half* __restrict__ WlB,
    const float* __restrict__ bias0, const float* __restrict__ bias1,
    const float* __restrict__ bias2,
    float* __restrict__ C,
    __half* __restrict__ Ch0, __half* __restrict__ Cl0,
    __half* __restrict__ Ch1, __half* __restrict__ Cl1,
    __half* __restrict__ Ch2, __half* __restrict__ Cl2,
    float oscale0, int M, int N, int K)
{
    extern __shared__ __half sm[];
    const int tid  = threadIdx.x;
    const int lane = tid & 31;
    const int wid  = tid >> 5;
    const int warp_m = wid >> 2;
    const int warp_n = wid & 3;
    const int which = blockIdx.x >> 4;               // 0..2 matrix selector
    const int n0 = (blockIdx.x & 15) * GN;
    const int m0 = blockIdx.y * GM;

    const __half* Wh = WhB + (size_t)which * WSZ;
    const __half* Wl = WlB + (size_t)which * WSZ;
    const float* bias = (which == 0) ? bias0 : (which == 1) ? bias1 : bias2;
    __half* Ch = (which == 0) ? Ch0 : (which == 1) ? Ch1 : Ch2;
    __half* Cl = (which == 0) ? Cl0 : (which == 1) ? Cl1 : Cl2;
    const float oscale = (which == 0) ? oscale0 : 1.0f;

    const uint32_t smb = smem_u32(sm);

    float acc[4][4][4];
    #pragma unroll
    for (int a = 0; a < 4; ++a)
        #pragma unroll
        for (int b = 0; b < 4; ++b)
            #pragma unroll
            for (int c = 0; c < 4; ++c) acc[a][b][c] = 0.0f;

    int lrow[4], lcol[4];
    #pragma unroll
    for (int i = 0; i < 4; ++i) {
        int linear = tid + i * 256;
        lrow[i] = linear >> 3;
        lcol[i] = (linear & 7) * 8;
    }

    auto load_chunk = [&](int ck, int s) {
        const int k0 = ck * KC;
        uint32_t stage_b = smb + (uint32_t)s * STAGE_ELEM * 2;
        const __half* gsrc[3] = {
            A + (size_t)m0 * K + k0,
            Wh + (size_t)n0 * K + k0, Wl + (size_t)n0 * K + k0 };
        #pragma unroll
        for (int t = 0; t < 3; ++t) {
            uint32_t tb = stage_b + (uint32_t)t * TELEM * 2;
            #pragma unroll
            for (int i = 0; i < 4; ++i) {
                uint32_t dst = tb + (uint32_t)(lrow[i] * GSTR + lcol[i]) * 2;
                const __half* src = gsrc[t] + (size_t)lrow[i] * K + lcol[i];
                CP_ASYNC16(dst, src);
            }
        }
    };

    load_chunk(0, 0); CP_COMMIT();
    load_chunk(1, 1); CP_COMMIT();

    const int arow  = warp_m * 64 + (lane & 15);
    const int aksel = (lane >> 4) << 3;
    const int brow  = warp_n * 32 + ((lane >> 4) << 3) + (lane & 7);
    const int bksel = ((lane >> 3) & 1) * 8;

    for (int ck = 0; ck < NCHUNK; ++ck) {
        const int s = ck & 1;
        CP_WAIT1();
        __syncthreads();

        uint32_t stage_b = smb + (uint32_t)s * STAGE_ELEM * 2;
        uint32_t bA  = stage_b;
        uint32_t bWh = stage_b + TELEM * 2;
        uint32_t bWl = stage_b + 2 * TELEM * 2;

        #pragma unroll
        for (int ks = 0; ks < KC / 16; ++ks) {
            const int akoff = ks * 16 + aksel;
            const int bkoff = ks * 16 + bksel;

            uint32_t af[4][4];
            #pragma unroll
            for (int a = 0; a < 4; ++a) {
                uint32_t off = (uint32_t)((arow + a * 16) * GSTR + akoff) * 2;
                LDMATRIX_X4(af[a][0], af[a][1], af[a][2], af[a][3], bA + off);
            }
            uint32_t bh[2][4], bl[2][4];
            #pragma unroll
            for (int p = 0; p < 2; ++p) {
                uint32_t off = (uint32_t)((brow + p * 16) * GSTR + bkoff) * 2;
                LDMATRIX_X4(bh[p][0], bh[p][1], bh[p][2], bh[p][3], bWh + off);
                LDMATRIX_X4(bl[p][0], bl[p][1], bl[p][2], bl[p][3], bWl + off);
            }
            #pragma unroll
            for (int a = 0; a < 4; ++a)
                #pragma unroll
                for (int p = 0; p < 2; ++p)
                    #pragma unroll
                    for (int hq = 0; hq < 2; ++hq) {
                        int nb = p * 2 + hq;
                        MMA_F16(acc[a][nb], af[a], bh[p][hq*2], bh[p][hq*2+1]);
                        MMA_F16(acc[a][nb], af[a], bl[p][hq*2], bl[p][hq*2+1]);
                    }
        }
        __syncthreads();
        if (ck + 2 < NCHUNK) load_chunk(ck + 2, s);
        CP_COMMIT();
    }

    // Epilogue
    #pragma unroll
    for (int a = 0; a < 4; ++a) {
        int r_lo = m0 + warp_m * 64 + a * 16 + (lane >> 2);
        #pragma unroll
        for (int nb = 0; nb < 4; ++nb) {
            int c = n0 + warp_n * 32 + nb * 8 + (lane & 3) * 2;
            float b0 = bias[c], b1 = bias[c + 1];
            float y00 = acc[a][nb][0] + b0, y01 = acc[a][nb][1] + b1;
            float y10 = acc[a][nb][2] + b0, y11 = acc[a][nb][3] + b1;
            if (Cl) {
                // fp16 hi/lo split output (K, V)
                uint32_t h, l;
                split2h(y00, y01, h, l);
                *reinterpret_cast<uint32_t*>(Ch + (size_t)r_lo * N + c) = h;
                *reinterpret_cast<uint32_t*>(Cl + (size_t)r_lo * N + c) = l;
                split2h(y10, y11, h, l);
                *reinterpret_cast<uint32_t*>(Ch + (size_t)(r_lo + 8) * N + c) = h;
                *reinterpret_cast<uint32_t*>(Cl + (size_t)(r_lo + 8) * N + c) = l;
            } else if (Ch) {
                // fp16 single output, scaled (Q)
                *reinterpret_cast<uint32_t*>(Ch + (size_t)r_lo * N + c) =
                    packh2(y00 * oscale, y01 * oscale);
                *reinterpret_cast<uint32_t*>(Ch + (size_t)(r_lo + 8) * N + c) =
                    packh2(y10 * oscale, y11 * oscale);
            } else {
                float2 v0 = { y00, y01 }, v1 = { y10, y11 };
                *reinterpret_cast<float2*>(C + (size_t)r_lo * N + c) = v0;
                *reinterpret_cast<float2*>(C + (size_t)(r_lo + 8) * N + c) = v1;
            }
        }
    }
}

// ===========================================================================
// Tensor-core flash attention — fp16 2-pass (Q single, K/V hi/lo, P single).
// BQ=128, 8 warps x 16 rows, warp-local softmax, register-resident P.
// ===========================================================================
#define FA_BQ   128
#define FA_BKV  64
#define FA_STR  136
#define FA_KT   (FA_BKV * FA_STR)      // 8704 elems per K/V half tile
#define FA_STAGE (4 * FA_KT)           // kh,kl,vh,vl
#define FA_QT   (FA_BQ * FA_STR)      // 17408 elems, Q single tile
#define FA_SMEM_B ((2 * FA_STAGE + FA_QT) * 2)   // 174080 bytes

__global__ __launch_bounds__(256, 1) void flash_mma(
    const __half* __restrict__ q16,
    const __half* __restrict__ kh, const __half* __restrict__ kl,
    const __half* __restrict__ vh, const __half* __restrict__ vl,
    __half* __restrict__ o16)
{
    extern __shared__ __half fsm[];
    const int tid  = threadIdx.x;
    const int lane = tid & 31;
    const int wid  = tid >> 5;
    const int q0   = blockIdx.x * FA_BQ;
    const int bh_i = blockIdx.y;
    const int b = bh_i >> 4, h = bh_i & 15;
    const size_t rowbase = (size_t)b * SEQ;
    const size_t cbase   = (size_t)h * HD;

    const uint32_t smb = smem_u32(fsm);
    const uint32_t Q_b = smb + 2 * FA_STAGE * 2;

    // Q tile loads: 128 rows x 16 granules (single fp16)
    #pragma unroll
    for (int i = 0; i < 8; ++i) {
        int g = tid + i * 256;
        int r = g >> 4, c = g & 15;
        size_t src = (rowbase + q0 + r) * HID + cbase + c * 8;
        uint32_t doff = (uint32_t)(r * FA_STR + c * 8) * 2;
        CP_ASYNC16(Q_b + doff, q16 + src);
    }
    CP_COMMIT();

    auto load_kv = [&](int ck, int s) {
        uint32_t stage_b = smb + (uint32_t)s * FA_STAGE * 2;
        const __half* gsrc[4] = { kh, kl, vh, vl };
        #pragma unroll
        for (int i = 0; i < 4; ++i) {
            int g = tid + i * 256;
            int r = g >> 4, c = g & 15;
            size_t src = (rowbase + ck * FA_BKV + r) * HID + cbase + c * 8;
            uint32_t doff = (uint32_t)(r * FA_STR + c * 8) * 2;
            #pragma unroll
            for (int t = 0; t < 4; ++t)
                CP_ASYNC16(stage_b + (uint32_t)t * FA_KT * 2 + doff, gsrc[t] + src);
        }
    };
    load_kv(0, 0); CP_COMMIT();
    load_kv(1, 1); CP_COMMIT();

    CP_WAIT2();
    __syncthreads();
    uint32_t qf[8][4];
    const int arow = wid * 16 + (lane & 15);
    const int aksel = (lane >> 4) << 3;
    #pragma unroll
    for (int ks = 0; ks < 8; ++ks) {
        uint32_t off = (uint32_t)(arow * FA_STR + ks * 16 + aksel) * 2;
        LDMATRIX_X4(qf[ks][0], qf[ks][1], qf[ks][2], qf[ks][3], Q_b + off);
    }

    float m0v = -1e30f, m1v = -1e30f, l0 = 0.0f, l1 = 0.0f;
    float acc_o[16][4];
    #pragma unroll
    for (int nf = 0; nf < 16; ++nf)
        #pragma unroll
        for (int c = 0; c < 4; ++c) acc_o[nf][c] = 0.0f;

    const int nrow  = ((lane >> 4) << 3) + (lane & 7);
    const int kksel = ((lane >> 3) & 1) * 8;
    const int vrow  = lane & 15;
    const int vcol8 = (lane >> 4) << 3;

    for (int ck = 0; ck < SEQ / FA_BKV; ++ck) {
        const int s = ck & 1;
        CP_WAIT1();
        __syncthreads();

        uint32_t stage_b = smb + (uint32_t)s * FA_STAGE * 2;
        uint32_t Kh_b = stage_b;
        uint32_t Kl_b = stage_b + FA_KT * 2;
        uint32_t Vh_b = stage_b + 2 * FA_KT * 2;
        uint32_t Vl_b = stage_b + 3 * FA_KT * 2;

        // S = Q Kh^T + Q Kl^T (2-pass)
        float accs[8][4];
        #pragma unroll
        for (int j = 0; j < 8; ++j)
            #pragma unroll
            for (int c = 0; c < 4; ++c) accs[j][c] = 0.0f;

        #pragma unroll
        for (int ks = 0; ks < 8; ++ks) {
            #pragma unroll
            for (int g4 = 0; g4 < 4; ++g4) {
                uint32_t off = (uint32_t)((g4 * 16 + nrow) * FA_STR + ks * 16 + kksel) * 2;
                uint32_t kbh[4], kbl[4];
                LDMATRIX_X4(kbh[0], kbh[1], kbh[2], kbh[3], Kh_b + off);
                LDMATRIX_X4(kbl[0], kbl[1], kbl[2], kbl[3], Kl_b + off);
                MMA_F16(accs[g4*2],   qf[ks], kbh[0], kbh[1]);
                MMA_F16(accs[g4*2],   qf[ks], kbl[0], kbl[1]);
                MMA_F16(accs[g4*2+1], qf[ks], kbh[2], kbh[3]);
                MMA_F16(accs[g4*2+1], qf[ks], kbl[2], kbl[3]);
            }
        }

        // online softmax (warp-local)
        float mx0 = -1e30f, mx1 = -1e30f;
        #pragma unroll
        for (int j = 0; j < 8; ++j) {
            mx0 = fmaxf(mx0, fmaxf(accs[j][0], accs[j][1]));
            mx1 = fmaxf(mx1, fmaxf(accs[j][2], accs[j][3]));
        }
        mx0 = fmaxf(mx0, __shfl_xor_sync(0xffffffffu, mx0, 1));
        mx0 = fmaxf(mx0, __shfl_xor_sync(0xffffffffu, mx0, 2));
        mx1 = fmaxf(mx1, __shfl_xor_sync(0xffffffffu, mx1, 1));
        mx1 = fmaxf(mx1, __shfl_xor_sync(0xffffffffu, mx1, 2));

        float mn0 = fmaxf(m0v, mx0), mn1 = fmaxf(m1v, mx1);
        float corr0 = __expf(m0v - mn0), corr1 = __expf(m1v - mn1);
        m0v = mn0; m1v = mn1;

        float sum0 = 0.0f, sum1 = 0.0f;
        #pragma unroll
        for (int j = 0; j < 8; ++j) {
            accs[j][0] = __expf(accs[j][0] - mn0);
            accs[j][1] = __expf(accs[j][1] - mn0);
            accs[j][2] = __expf(accs[j][2] - mn1);
            accs[j][3] = __expf(accs[j][3] - mn1);
            sum0 += accs[j][0] + accs[j][1];
            sum1 += accs[j][2] + accs[j][3];
        }
        sum0 += __shfl_xor_sync(0xffffffffu, sum0, 1);
        sum0 += __shfl_xor_sync(0xffffffffu, sum0, 2);
        sum1 += __shfl_xor_sync(0xffffffffu, sum1, 1);
        sum1 += __shfl_xor_sync(0xffffffffu, sum1, 2);
        l0 = l0 * corr0 + sum0;
        l1 = l1 * corr1 + sum1;

        #pragma unroll
        for (int nf = 0; nf < 16; ++nf) {
            acc_o[nf][0] *= corr0; acc_o[nf][1] *= corr0;
            acc_o[nf][2] *= corr1; acc_o[nf][3] *= corr1;
        }

        // P fragments (single fp16 from registers)
        uint32_t pf[4][4];
        #pragma unroll
        for (int t = 0; t < 4; ++t) {
            int j0 = 2 * t, j1 = 2 * t + 1;
            pf[t][0] = packh2(accs[j0][0], accs[j0][1]);
            pf[t][1] = packh2(accs[j0][2], accs[j0][3]);
            pf[t][2] = packh2(accs[j1][0], accs[j1][1]);
            pf[t][3] = packh2(accs[j1][2], accs[j1][3]);
        }

        // O += P Vh + P Vl (2-pass); V via ldmatrix.trans
        #pragma unroll
        for (int t = 0; t < 4; ++t) {
            #pragma unroll
            for (int g8 = 0; g8 < 8; ++g8) {
                uint32_t off = (uint32_t)((t * 16 + vrow) * FA_STR + g8 * 16 + vcol8) * 2;
                uint32_t vbh[4], vbl[4];
                LDMATRIX_X4_T(vbh[0], vbh[1], vbh[2], vbh[3], Vh_b + off);
                LDMATRIX_X4_T(vbl[0], vbl[1], vbl[2], vbl[3], Vl_b + off);
                int nf0 = g8 * 2, nf1 = nf0 + 1;
                MMA_F16(acc_o[nf0], pf[t], vbh[0], vbh[1]);
                MMA_F16(acc_o[nf0], pf[t], vbl[0], vbl[1]);
                MMA_F16(acc_o[nf1], pf[t], vbh[2], vbh[3]);
                MMA_F16(acc_o[nf1], pf[t], vbl[2], vbl[3]);
            }
        }

        __syncthreads();
        if (ck + 2 < SEQ / FA_BKV) load_kv(ck + 2, s);
        CP_COMMIT();
    }

    // epilogue: normalize, single fp16 output
    float inv0 = 1.0f / l0, inv1 = 1.0f / l1;
    int r0 = q0 + wid * 16 + (lane >> 2);
    int r1 = r0 + 8;
    #pragma unroll
    for (int g8 = 0; g8 < 8; ++g8) {
        #pragma unroll
        for (int half = 0; half < 2; ++half) {
            int nf = g8 * 2 + half;
            int c = g8 * 16 + half * 8 + (lane & 3) * 2;
            size_t o0 = (rowbase + r0) * HID + cbase + c;
            size_t o1 = (rowbase + r1) * HID + cbase + c;
            *reinterpret_cast<uint32_t*>(o16 + o0) =
                packh2(acc_o[nf][0] * inv0, acc_o[nf][1] * inv0);
            *reinterpret_cast<uint32_t*>(o16 + o1) =
                packh2(acc_o[nf][2] * inv1, acc_o[nf][3] * inv1);
        }
    }
}

// ---------------------------------------------------------------------------
// Launch
// ---------------------------------------------------------------------------
extern "C" void kernel_launch(void* const* d_in, const int* in_sizes, int n_in,
                              void* d_out, int out_size)
{
    const float* x  = (const float*)d_in[0];
    const float* Wq = (const float*)d_in[1];
    const float* bq = (const float*)d_in[2];
    const float* Wk = (const float*)d_in[3];
    const float* bk = (const float*)d_in[4];
    const float* Wv = (const float*)d_in[5];
    const float* bv = (const float*)d_in[6];
    const float* Wo = (const float*)d_in[7];
    const float* bo = (const float*)d_in[8];
    float* out = (float*)d_out;

    __half *x16, *a16, *Whb, *Wlb, *q16, *kh, *kl, *vh, *vl;
    cudaGetSymbolAddress((void**)&x16, g_x16);
    cudaGetSymbolAddress((void**)&a16, g_a16);
    cudaGetSymbolAddress((void**)&Whb, g_Wh);
    cudaGetSymbolAddress((void**)&Wlb, g_Wl);
    cudaGetSymbolAddress((void**)&q16, g_q16);
    cudaGetSymbolAddress((void**)&kh, g_kh);
    cudaGetSymbolAddress((void**)&kl, g_kl);
    cudaGetSymbolAddress((void**)&vh, g_vh);
    cudaGetSymbolAddress((void**)&vl, g_vl);

    cudaFuncSetAttribute(gemm_mma,
                         cudaFuncAttributeMaxDynamicSharedMemorySize, GEMM_SMEM_B);
    cudaFuncSetAttribute(flash_mma,
                         cudaFuncAttributeMaxDynamicSharedMemorySize, FA_SMEM_B);

    // Conversions: x -> fp16; W's -> fp16 hi/lo
    const int n4x = (int)(MSZ / 4), n4w = (int)(WSZ / 4);
    cvt_f16_kernel<<<(n4x + 255) / 256, 256>>>(x, x16, n4x);
    const float* Ws[4] = { Wq, Wk, Wv, Wo };
    for (int i = 0; i < 4; ++i)
        split_f16hl_kernel<<<(n4w + 255) / 256, 256>>>(
            Ws[i], Whb + (size_t)i * WSZ, Wlb + (size_t)i * WSZ, n4w);

    const float scale = 1.0f / sqrtf((float)HD);

    // Fused Q/K/V projections: Q -> single fp16 (scaled), K/V -> fp16 hi/lo
    dim3 qkv_grid(3 * (HID / GN), MROWS / GM);   // (48, 32)
    gemm_mma<<<qkv_grid, 256, GEMM_SMEM_B>>>(
        x16, Whb, Wlb, bq, bk, bv,
        nullptr,
        q16, nullptr,        // which=0: Q single fp16
        kh, kl,              // which=1: K hi/lo
        vh, vl,              // which=2: V hi/lo
        scale, MROWS, HID, HID);

    dim3 fgrid(SEQ / FA_BQ, BATCH * HEADS);  // (16, 32)
    flash_mma<<<fgrid, 256, FA_SMEM_B>>>(q16, kh, kl, vh, vl, a16);

    // Output projection -> f32 result
    dim3 ogrid(HID / GN, MROWS / GM);   // (16, 32)
    gemm_mma<<<ogrid, 256, GEMM_SMEM_B>>>(
        a16, Whb + 3 * WSZ, Wlb + 3 * WSZ, bo, nullptr, nullptr,
        out, nullptr, nullptr, nullptr, nullptr, nullptr, nullptr,
        1.0f, MROWS, HID, HID);
}